// round 1
// baseline (speedup 1.0000x reference)
#include <cuda_runtime.h>
#include <math.h>

// Problem constants
// x: (8,96,128,128) f32; w: (192,96,3,3) f32; beta scalar f32
// out: (8,48,256,256) f32
#define PI_F 3.14159265358979f

static const int NPIX = 8 * 48 * 256 * 256; // 25165824

// Scratch (allowed: __device__ globals, no runtime alloc)
__device__ float  g_y[25165824];          // conv output in pixel-shuffled layout
__device__ float4 g_u4[25165824 / 2];     // row-filtered complex field (float2 pairs)

// ---------------------------------------------------------------------------
// complex helpers
// ---------------------------------------------------------------------------
__device__ __forceinline__ float2 cadd(float2 a, float2 b) { return make_float2(a.x + b.x, a.y + b.y); }
__device__ __forceinline__ float2 csub(float2 a, float2 b) { return make_float2(a.x - b.x, a.y - b.y); }
__device__ __forceinline__ float2 cmul(float2 a, float2 b) {
    return make_float2(a.x * b.x - a.y * b.y, a.x * b.y + a.y * b.x);
}
__device__ __forceinline__ float2 expi(float a) {
    float s, c; __sincosf(a, &s, &c); // fast version; refine below
    // use precise for accuracy
    s = sinf(a); c = cosf(a);
    return make_float2(c, s);
}
__device__ __forceinline__ float2 shflxc(float2 v, int m) {
    v.x = __shfl_xor_sync(0xffffffffu, v.x, m);
    v.y = __shfl_xor_sync(0xffffffffu, v.y, m);
    return v;
}

struct FTw {
    float2 ws[5];  // stage twiddles for S=16,8,4,2,1 (forward sign)
    float2 m[8];   // mid twiddles W_256^(j*brev5(lane)), forward sign
};

__device__ __forceinline__ void make_tw(int lane, FTw& t) {
    int brl = __brev((unsigned)lane) >> 27;  // bitrev5
    t.ws[0] = expi(-PI_F * (float)(lane & 15) / 16.0f);
    t.ws[1] = expi(-PI_F * (float)(lane & 7) / 8.0f);
    t.ws[2] = expi(-PI_F * (float)(lane & 3) / 4.0f);
    t.ws[3] = expi(-PI_F * (float)(lane & 1) / 2.0f);
    t.ws[4] = make_float2(1.0f, 0.0f);
    float2 mb = expi(-2.0f * PI_F * (float)brl / 256.0f);
    t.m[0] = make_float2(1.0f, 0.0f);
#pragma unroll
    for (int j = 1; j < 8; j++) t.m[j] = cmul(t.m[j - 1], mb);
}

// Forward 256-pt FFT. Input: lane l, reg j holds x[8l+j] (natural order).
// Output: lane l, reg j holds X[brev5(l) + 32*brev3(j)] (scrambled, fine).
__device__ __forceinline__ void fft_fwd(float2 d[8], const FTw& t, int lane) {
    // cross-lane DIF-32 over n1
#pragma unroll
    for (int s = 0; s < 5; s++) {
        int S = 16 >> s;
        float2 w = t.ws[s];
        bool hi = (lane & S) != 0;
#pragma unroll
        for (int j = 0; j < 8; j++) {
            float2 o = shflxc(d[j], S);
            d[j] = hi ? cmul(csub(o, d[j]), w) : cadd(d[j], o);
        }
    }
    // mid twiddles
#pragma unroll
    for (int j = 1; j < 8; j++) d[j] = cmul(d[j], t.m[j]);
    // in-register DIF-8 over n2
    const float R = 0.70710678118654752f;
    const float2 W81 = make_float2(R, -R);
    const float2 W83 = make_float2(-R, -R);
    {   // S=4
        float2 u, v, tt;
        u = d[0]; v = d[4]; d[0] = cadd(u, v); d[4] = csub(u, v);
        u = d[1]; v = d[5]; d[1] = cadd(u, v); d[5] = cmul(csub(u, v), W81);
        u = d[2]; v = d[6]; d[2] = cadd(u, v); tt = csub(u, v); d[6] = make_float2(tt.y, -tt.x); // * -i
        u = d[3]; v = d[7]; d[3] = cadd(u, v); d[7] = cmul(csub(u, v), W83);
    }
#pragma unroll
    for (int g = 0; g < 8; g += 4) { // S=2
        float2 u, v, tt;
        u = d[g];     v = d[g + 2]; d[g] = cadd(u, v);     d[g + 2] = csub(u, v);
        u = d[g + 1]; v = d[g + 3]; tt = csub(u, v);
        d[g + 1] = cadd(u, v); d[g + 3] = make_float2(tt.y, -tt.x); // * -i
    }
#pragma unroll
    for (int g = 0; g < 8; g += 2) { // S=1
        float2 u = d[g], v = d[g + 1];
        d[g] = cadd(u, v); d[g + 1] = csub(u, v);
    }
}

// Inverse (unscaled by 256): exact inverse network of fft_fwd.
__device__ __forceinline__ void fft_inv(float2 d[8], const FTw& t, int lane) {
    const float R = 0.70710678118654752f;
    const float2 W81c = make_float2(R, R);    // conj(W8^1)
    const float2 W83c = make_float2(-R, R);   // conj(W8^3)
    // inverse in-register DIF-8: S=1, then S=2, then S=4 (conj twiddles)
#pragma unroll
    for (int g = 0; g < 8; g += 2) {
        float2 a = d[g], b = d[g + 1];
        d[g] = cadd(a, b); d[g + 1] = csub(a, b);
    }
#pragma unroll
    for (int g = 0; g < 8; g += 4) {
        float2 a, b, vb;
        a = d[g];     b = d[g + 2]; d[g] = cadd(a, b); d[g + 2] = csub(a, b);
        a = d[g + 1]; b = d[g + 3]; vb = make_float2(-b.y, b.x); // i*b
        d[g + 1] = cadd(a, vb); d[g + 3] = csub(a, vb);
    }
    {
        float2 a, v;
        a = d[0]; v = d[4];                d[0] = cadd(a, v); d[4] = csub(a, v);
        a = d[1]; v = cmul(d[5], W81c);    d[1] = cadd(a, v); d[5] = csub(a, v);
        a = d[2]; { float2 b = d[6]; v = make_float2(-b.y, b.x); } d[2] = cadd(a, v); d[6] = csub(a, v);
        a = d[3]; v = cmul(d[7], W83c);    d[3] = cadd(a, v); d[7] = csub(a, v);
    }
    // conj mid twiddles
#pragma unroll
    for (int j = 1; j < 8; j++) {
        float2 mc = make_float2(t.m[j].x, -t.m[j].y);
        d[j] = cmul(d[j], mc);
    }
    // inverse cross-lane: S=1,2,4,8,16 with conj twiddles
#pragma unroll
    for (int s = 0; s < 5; s++) {
        int S = 1 << s;
        float2 w = t.ws[4 - s];
        float2 wc = make_float2(w.x, -w.y);
        bool hi = (lane & S) != 0;
#pragma unroll
        for (int j = 0; j < 8; j++) {
            float2 pre = hi ? cmul(d[j], wc) : d[j];
            float2 o = shflxc(pre, S);
            d[j] = hi ? csub(o, pre) : cadd(pre, o);
        }
    }
}

// Half-band mask in scrambled domain: keep k2=brev3(j) in {0,1,6,7} => zero regs {1,2,5,6}
__device__ __forceinline__ void apply_mask(float2 d[8]) {
    d[1] = make_float2(0.f, 0.f);
    d[2] = make_float2(0.f, 0.f);
    d[5] = make_float2(0.f, 0.f);
    d[6] = make_float2(0.f, 0.f);
}

// ---------------------------------------------------------------------------
// K1: 3x3 conv, pad 1, writes directly to pixel-shuffled layout g_y
// grid (64 tiles, 12 oc-groups, 8 batch), 256 threads
// ---------------------------------------------------------------------------
__global__ void __launch_bounds__(256) conv_kernel(const float* __restrict__ x,
                                                   const float* __restrict__ wgt) {
    __shared__ float s_in[16][10][36];
    __shared__ float s_wt[16][16][9];
    int t = threadIdx.x;
    int tileId = blockIdx.x;
    int tw = tileId & 3, th = tileId >> 2;
    int ocg = blockIdx.y, b = blockIdx.z;
    int ocsub = t >> 6;               // 0..3 -> 4 oc each
    int sp = t & 63;
    int sx = sp & 7, sy = sp >> 3;    // sx: 8 groups of 4 px, sy: 8 rows
    int h = th * 8 + sy;
    int w0 = tw * 32 + sx * 4;

    float acc[4][4];
#pragma unroll
    for (int o = 0; o < 4; o++)
#pragma unroll
        for (int p = 0; p < 4; p++) acc[o][p] = 0.0f;

    for (int ch = 0; ch < 6; ch++) {
        // input tile: 16 ic x 10 rows x 34 cols (with zero halo)
        for (int idx = t; idx < 16 * 10 * 34; idx += 256) {
            int icl = idx / 340;
            int rem = idx - icl * 340;
            int ihh = rem / 34;
            int iww = rem - ihh * 34;
            int gh = th * 8 + ihh - 1;
            int gw = tw * 32 + iww - 1;
            float v = 0.0f;
            if (gh >= 0 && gh < 128 && gw >= 0 && gw < 128)
                v = x[(((size_t)b * 96 + ch * 16 + icl) * 128 + gh) * 128 + gw];
            s_in[icl][ihh][iww] = v;
        }
        // weights: 16 oc x 16 ic x 9
        for (int idx = t; idx < 2304; idx += 256) {
            int o = idx / 144;
            int rem = idx - o * 144;
            int icl = rem / 9;
            int k = rem - icl * 9;
            s_wt[o][icl][k] = wgt[((size_t)(ocg * 16 + o) * 96 + ch * 16 + icl) * 9 + k];
        }
        __syncthreads();

        for (int icl = 0; icl < 16; icl++) {
            float rin[3][6];
#pragma unroll
            for (int kh = 0; kh < 3; kh++) {
                const float2* rp = (const float2*)&s_in[icl][sy + kh][sx * 4];
#pragma unroll
                for (int cI = 0; cI < 3; cI++) {
                    float2 v2 = rp[cI];
                    rin[kh][cI * 2] = v2.x;
                    rin[kh][cI * 2 + 1] = v2.y;
                }
            }
#pragma unroll
            for (int o = 0; o < 4; o++) {
                const float* wp = s_wt[ocsub * 4 + o][icl];
                float w00 = wp[0], w01 = wp[1], w02 = wp[2];
                float w10 = wp[3], w11 = wp[4], w12 = wp[5];
                float w20 = wp[6], w21 = wp[7], w22 = wp[8];
#pragma unroll
                for (int px = 0; px < 4; px++) {
                    float a = acc[o][px];
                    a = fmaf(rin[0][px], w00, a);
                    a = fmaf(rin[0][px + 1], w01, a);
                    a = fmaf(rin[0][px + 2], w02, a);
                    a = fmaf(rin[1][px], w10, a);
                    a = fmaf(rin[1][px + 1], w11, a);
                    a = fmaf(rin[1][px + 2], w12, a);
                    a = fmaf(rin[2][px], w20, a);
                    a = fmaf(rin[2][px + 1], w21, a);
                    a = fmaf(rin[2][px + 2], w22, a);
                    acc[o][px] = a;
                }
            }
        }
        __syncthreads();
    }

    // write to pixel-shuffled layout: ps[b][oc>>2][2h+((oc>>1)&1)][2w+(oc&1)]
#pragma unroll
    for (int o = 0; o < 4; o++) {
        int oc = ocg * 16 + ocsub * 4 + o;
        int cch = oc >> 2;
        int p = (oc >> 1) & 1;
        int q = oc & 1;
        size_t rowbase = (((size_t)b * 48 + cch) * 256 + (2 * h + p)) * 256;
#pragma unroll
        for (int px = 0; px < 4; px++) {
            g_y[rowbase + 2 * (size_t)(w0 + px) + q] = acc[o][px];
        }
    }
}

// ---------------------------------------------------------------------------
// K2: row pass. Each warp: 16 rows, H = IFFT*M*FFT per 256-float row.
// grid 768, 256 threads (8 warps)
// ---------------------------------------------------------------------------
__global__ void __launch_bounds__(256) row_kernel() {
    int lane = threadIdx.x & 31;
    int wp = threadIdx.x >> 5;
    FTw t;
    make_tw(lane, t);
    int base = (blockIdx.x * 8 + wp) * 16;
    const float sc = 1.0f / 256.0f;
    for (int i = 0; i < 16; i++) {
        int row = base + i;
        const float4* yr = (const float4*)(g_y + (size_t)row * 256);
        float4 a = yr[lane * 2 + 0];
        float4 bq = yr[lane * 2 + 1];
        float2 d[8];
        d[0] = make_float2(a.x, 0.f);  d[1] = make_float2(a.y, 0.f);
        d[2] = make_float2(a.z, 0.f);  d[3] = make_float2(a.w, 0.f);
        d[4] = make_float2(bq.x, 0.f); d[5] = make_float2(bq.y, 0.f);
        d[6] = make_float2(bq.z, 0.f); d[7] = make_float2(bq.w, 0.f);
        fft_fwd(d, t, lane);
        apply_mask(d);
        fft_inv(d, t, lane);
        float4* ur = (float4*)(g_u4 + (size_t)row * 128);
        ur[lane * 4 + 0] = make_float4(d[0].x * sc, d[0].y * sc, d[1].x * sc, d[1].y * sc);
        ur[lane * 4 + 1] = make_float4(d[2].x * sc, d[2].y * sc, d[3].x * sc, d[3].y * sc);
        ur[lane * 4 + 2] = make_float4(d[4].x * sc, d[4].y * sc, d[5].x * sc, d[5].y * sc);
        ur[lane * 4 + 3] = make_float4(d[6].x * sc, d[6].y * sc, d[7].x * sc, d[7].y * sc);
    }
}

// ---------------------------------------------------------------------------
// K3: column pass + magnitude + combine.
// grid 384*16 (img, 16-col tile), 256 threads. smem tile with permuted row
// layout perm(r) = (r&7)*32 + (r>>3) so warp FFT column reads are conflict-free.
// ---------------------------------------------------------------------------
__global__ void __launch_bounds__(256) col_kernel(const float* __restrict__ beta,
                                                  float* __restrict__ out) {
    __shared__ float2 tile[16][257];
    int t = threadIdx.x;
    int img = blockIdx.x >> 4;
    int c0 = (blockIdx.x & 15) << 4;
    size_t ibase = (size_t)img * 65536;
    const float2* u2 = (const float2*)g_u4;

    int cL = t & 15;
    int rg = t >> 4;
    for (int k = 0; k < 16; k++) {
        int r = rg + k * 16;
        tile[cL][((r & 7) << 5) | (r >> 3)] = u2[ibase + (size_t)r * 256 + c0 + cL];
    }
    __syncthreads();

    int lane = t & 31;
    int wp = t >> 5;
    FTw tw;
    make_tw(lane, tw);
    const float sc = 1.0f / 256.0f;
    for (int cc = 0; cc < 2; cc++) {
        int cl = wp + cc * 8;
        float2 d[8];
#pragma unroll
        for (int j = 0; j < 8; j++) d[j] = tile[cl][j * 32 + lane];
        fft_fwd(d, tw, lane);
        apply_mask(d);
        fft_inv(d, tw, lane);
#pragma unroll
        for (int j = 0; j < 8; j++) {
            float vx = d[j].x * sc, vy = d[j].y * sc;
            tile[cl][j * 32 + lane].x = sqrtf(vx * vx + vy * vy);
        }
    }
    __syncthreads();

    float be = *beta;
    float a0 = be;
    float a1 = 1.0f - 2.0f * be;
    for (int k = 0; k < 16; k++) {
        int idx = k * 256 + t;
        int r = idx >> 4;
        int c = idx & 15;
        size_t g = ibase + (size_t)r * 256 + c0 + c;
        out[g] = a0 * g_y[g] + a1 * tile[c][((r & 7) << 5) | (r >> 3)].x;
    }
}

// ---------------------------------------------------------------------------
extern "C" void kernel_launch(void* const* d_in, const int* in_sizes, int n_in,
                              void* d_out, int out_size) {
    const float* x = (const float*)d_in[0];
    const float* w = (const float*)d_in[1];
    const float* beta = (const float*)d_in[2];
    float* out = (float*)d_out;

    conv_kernel<<<dim3(64, 12, 8), 256>>>(x, w);
    row_kernel<<<768, 256>>>();
    col_kernel<<<384 * 16, 256>>>(beta, out);
}

// round 3
// speedup vs baseline: 2.2660x; 2.2660x over previous
#include <cuda_runtime.h>
#include <cuda_bf16.h>
#include <math.h>
#include <stdint.h>

#define PI_F 3.14159265358979f

// ---------------------------------------------------------------------------
// Scratch (__device__ globals; no runtime alloc)
// ---------------------------------------------------------------------------
__device__ float  g_y[25165824];               // conv output, pixel-shuffled (8,48,256,256)
__device__ float4 g_u4[25165824 / 2];          // row-filtered complex field
__device__ __nv_bfloat16 g_xh[12582912];       // x transposed [b][hw][ic], bf16 hi
__device__ __nv_bfloat16 g_xl[12582912];       // bf16 lo residual
__device__ __nv_bfloat16 g_wimg[497664];       // weights: 54 chunks x {hi[192][24], lo[192][24]}

// ---------------------------------------------------------------------------
// mma.sync wrapper (bf16, m16n8k16) — non-"a" feature, works at compute_103
// ---------------------------------------------------------------------------
__device__ __forceinline__ void mma16816(float c[4],
                                         uint32_t a0, uint32_t a1, uint32_t a2, uint32_t a3,
                                         uint32_t b0, uint32_t b1) {
    asm volatile(
        "mma.sync.aligned.m16n8k16.row.col.f32.bf16.bf16.f32 "
        "{%0,%1,%2,%3}, {%4,%5,%6,%7}, {%8,%9}, {%0,%1,%2,%3};"
        : "+f"(c[0]), "+f"(c[1]), "+f"(c[2]), "+f"(c[3])
        : "r"(a0), "r"(a1), "r"(a2), "r"(a3), "r"(b0), "r"(b1));
}

__device__ __forceinline__ uint32_t smem_u32(const void* p) {
    uint32_t a;
    asm("{ .reg .u64 t; cvta.to.shared.u64 t, %1; cvt.u32.u64 %0, t; }" : "=r"(a) : "l"(p));
    return a;
}
__device__ __forceinline__ void cp_async16(uint32_t dst, const void* src) {
    asm volatile("cp.async.cg.shared.global [%0], [%1], 16;" :: "r"(dst), "l"(src));
}
__device__ __forceinline__ void cp_commit() { asm volatile("cp.async.commit_group;"); }
__device__ __forceinline__ void cp_wait0()  { asm volatile("cp.async.wait_group 0;"); }

// ---------------------------------------------------------------------------
// Prep 1: weights -> bf16 hi/lo images per k16 chunk.
// chunk c = tap*6 + icg, tap = kh*3+kw. Layout per chunk (elem offsets):
//   hi: c*9216 + oc*24 + j  (j<16 valid, j>=16 zero pad)
//   lo: c*9216 + 4608 + oc*24 + j
// ---------------------------------------------------------------------------
__global__ void wprep_kernel(const float* __restrict__ wgt) {
    int i = blockIdx.x * 256 + threadIdx.x;
    if (i >= 248832) return;
    int j = i % 24;
    int oc = (i / 24) % 192;
    int c = i / (24 * 192);
    int tap = c / 6, icg = c % 6;
    int kh = tap / 3, kw = tap % 3;
    float w = 0.0f;
    if (j < 16) {
        int ic = icg * 16 + j;
        w = wgt[((size_t)oc * 96 + ic) * 9 + kh * 3 + kw];
    }
    __nv_bfloat16 hi = __float2bfloat16(w);
    __nv_bfloat16 lo = __float2bfloat16(w - __bfloat162float(hi));
    g_wimg[c * 9216 + oc * 24 + j] = hi;
    g_wimg[c * 9216 + 4608 + oc * 24 + j] = lo;
}

// ---------------------------------------------------------------------------
// Prep 2: transpose x (b,ic,h,w) f32 -> (b, hw, ic) bf16 hi/lo.
// grid (512 hw-tiles, 3 icg, 8 b), 256 threads, 32x32 tiles.
// ---------------------------------------------------------------------------
__global__ void __launch_bounds__(256) xprep_kernel(const float* __restrict__ x) {
    __shared__ float tile[32][33];
    int t = threadIdx.x;
    int j = t & 31, i4 = t >> 5;
    int hw0 = blockIdx.x * 32;
    int ic0 = blockIdx.y * 32;
    int b = blockIdx.z;
#pragma unroll
    for (int r = 0; r < 4; r++) {
        int ic = ic0 + i4 * 4 + r;
        tile[i4 * 4 + r][j] = x[((size_t)b * 96 + ic) * 16384 + hw0 + j];
    }
    __syncthreads();
#pragma unroll
    for (int r = 0; r < 4; r++) {
        int hwl = i4 * 4 + r;
        float v = tile[j][hwl];
        __nv_bfloat16 hi = __float2bfloat16(v);
        __nv_bfloat16 lo = __float2bfloat16(v - __bfloat162float(hi));
        size_t idx = ((size_t)b * 16384 + hw0 + hwl) * 96 + ic0 + j;
        g_xh[idx] = hi;
        g_xl[idx] = lo;
    }
}

// ---------------------------------------------------------------------------
// Conv via mma.sync implicit GEMM. CTA = (h, b): D[192 oc][128 w-px], K=864.
// xs smem: [3 kh][130 ww][104 ic-pad] bf16 (hi & lo), ww = w + 1 (halo).
// weights: 2-slot cp.async ring, each slot = one chunk {hi[192][24], lo[192][24]}.
// 256 threads = 8 warps: warp = (ocg2 = wid>>2) x (pxg = wid&3):
//   warp tile = 96 oc (6 m16) x 32 px (4 n8); split products x3.
// ---------------------------------------------------------------------------
#define XS_ELEMS 40560              // 3*130*104
#define WSLOT_OFF_B 162240          // bytes: 2 * XS_ELEMS * 2
#define SLOT_BYTES 18432            // 9216 bf16
#define CONV_SMEM (WSLOT_OFF_B + 2 * SLOT_BYTES)

__global__ void __launch_bounds__(256) conv_mma_kernel() {
    extern __shared__ char sd[];
    __nv_bfloat16* xsH = (__nv_bfloat16*)sd;
    __nv_bfloat16* xsL = xsH + XS_ELEMS;
    __nv_bfloat16* wring = (__nv_bfloat16*)(sd + WSLOT_OFF_B);

    int t = threadIdx.x;
    int h = blockIdx.x;
    int b = blockIdx.y;
    int wid = t >> 5, lane = t & 31;
    int g = lane >> 2, tig = lane & 3;
    int ocbase = (wid >> 2) * 96;
    int pxbase = (wid & 3) * 32;

    // Preload chunk 0 weights
    uint32_t wring_s = smem_u32(wring);
    for (int i = t; i < 1152; i += 256)
        cp_async16(wring_s + i * 16, (const char*)g_wimg + i * 16);
    cp_commit();

    // Stage input rows (hi & lo) with halo
    {
        const __nv_bfloat16* xb_h = g_xh + (size_t)b * 16384 * 96;
        const __nv_bfloat16* xb_l = g_xl + (size_t)b * 16384 * 96;
        for (int idx = t; idx < 4680; idx += 256) {
            int c16 = idx % 12;
            int ww = (idx / 12) % 130;
            int kh = idx / (12 * 130);
            int hp = h + kh - 1;
            int wp = ww - 1;
            uint4 vh = make_uint4(0, 0, 0, 0), vl = vh;
            if (hp >= 0 && hp < 128 && wp >= 0 && wp < 128) {
                size_t src = ((size_t)hp * 128 + wp) * 96 + c16 * 8;
                vh = *(const uint4*)(xb_h + src);
                vl = *(const uint4*)(xb_l + src);
            }
            int dst = kh * 13520 + ww * 104 + c16 * 8;
            *(uint4*)(xsH + dst) = vh;
            *(uint4*)(xsL + dst) = vl;
        }
    }
    cp_wait0();
    __syncthreads();

    float acc[6][4][4];
#pragma unroll
    for (int m = 0; m < 6; m++)
#pragma unroll
        for (int n = 0; n < 4; n++)
#pragma unroll
            for (int q = 0; q < 4; q++) acc[m][n][q] = 0.0f;

    for (int c = 0; c < 54; c++) {
        // prefetch next chunk into other slot
        if (c < 53) {
            uint32_t dsts = wring_s + ((c + 1) & 1) * SLOT_BYTES;
            const char* srcg = (const char*)g_wimg + (size_t)(c + 1) * SLOT_BYTES;
            for (int i = t; i < 1152; i += 256)
                cp_async16(dsts + i * 16, srcg + i * 16);
            cp_commit();
        }

        int tap = c / 6, icg = c % 6;
        int kh = tap / 3, kw = tap % 3;
        const __nv_bfloat16* wslot = wring + (c & 1) * 9216;

        // B fragments (input), hi & lo
        uint32_t bh0[4], bh1[4], bl0[4], bl1[4];
        int rowb = kh * 130 + pxbase + kw + g;
        int icoff = icg * 16 + 2 * tig;
#pragma unroll
        for (int n = 0; n < 4; n++) {
            int off = (rowb + n * 8) * 104 + icoff;
            bh0[n] = *(const uint32_t*)(xsH + off);
            bh1[n] = *(const uint32_t*)(xsH + off + 8);
            bl0[n] = *(const uint32_t*)(xsL + off);
            bl1[n] = *(const uint32_t*)(xsL + off + 8);
        }
#pragma unroll
        for (int m = 0; m < 6; m++) {
            const __nv_bfloat16* pA = wslot + (ocbase + m * 16 + g) * 24 + 2 * tig;
            uint32_t ah0 = *(const uint32_t*)pA;
            uint32_t ah1 = *(const uint32_t*)(pA + 192);
            uint32_t ah2 = *(const uint32_t*)(pA + 8);
            uint32_t ah3 = *(const uint32_t*)(pA + 200);
            uint32_t al0 = *(const uint32_t*)(pA + 4608);
            uint32_t al1 = *(const uint32_t*)(pA + 4800);
            uint32_t al2 = *(const uint32_t*)(pA + 4616);
            uint32_t al3 = *(const uint32_t*)(pA + 4808);
#pragma unroll
            for (int n = 0; n < 4; n++) {
                mma16816(acc[m][n], ah0, ah1, ah2, ah3, bh0[n], bh1[n]);
                mma16816(acc[m][n], ah0, ah1, ah2, ah3, bl0[n], bl1[n]);
                mma16816(acc[m][n], al0, al1, al2, al3, bh0[n], bh1[n]);
            }
        }
        if (c < 53) cp_wait0();
        __syncthreads();
    }

    // Epilogue: scatter into pixel-shuffled g_y
#pragma unroll
    for (int m = 0; m < 6; m++) {
        int ocr = ocbase + m * 16 + g;
#pragma unroll
        for (int n = 0; n < 4; n++) {
            int px = pxbase + n * 8 + 2 * tig;
#pragma unroll
            for (int q = 0; q < 4; q++) {
                int oc = ocr + (q >> 1) * 8;
                int pxx = px + (q & 1);
                int cch = oc >> 2;
                int pbit = (oc >> 1) & 1;
                int qbit = oc & 1;
                g_y[(((size_t)b * 48 + cch) * 256 + (2 * h + pbit)) * 256 + 2 * pxx + qbit] =
                    acc[m][n][q];
            }
        }
    }
}

// ---------------------------------------------------------------------------
// Warp FFT machinery (row-1 proven)
// ---------------------------------------------------------------------------
__device__ __forceinline__ float2 cadd(float2 a, float2 b) { return make_float2(a.x + b.x, a.y + b.y); }
__device__ __forceinline__ float2 csub(float2 a, float2 b) { return make_float2(a.x - b.x, a.y - b.y); }
__device__ __forceinline__ float2 cmul(float2 a, float2 b) {
    return make_float2(a.x * b.x - a.y * b.y, a.x * b.y + a.y * b.x);
}
__device__ __forceinline__ float2 expi(float a) { return make_float2(cosf(a), sinf(a)); }
__device__ __forceinline__ float2 shflxc(float2 v, int m) {
    v.x = __shfl_xor_sync(0xffffffffu, v.x, m);
    v.y = __shfl_xor_sync(0xffffffffu, v.y, m);
    return v;
}

struct FTw { float2 ws[5]; float2 m[8]; };

__device__ __forceinline__ void make_tw(int lane, FTw& t) {
    int brl = __brev((unsigned)lane) >> 27;
    t.ws[0] = expi(-PI_F * (float)(lane & 15) / 16.0f);
    t.ws[1] = expi(-PI_F * (float)(lane & 7) / 8.0f);
    t.ws[2] = expi(-PI_F * (float)(lane & 3) / 4.0f);
    t.ws[3] = expi(-PI_F * (float)(lane & 1) / 2.0f);
    t.ws[4] = make_float2(1.0f, 0.0f);
    float2 mb = expi(-2.0f * PI_F * (float)brl / 256.0f);
    t.m[0] = make_float2(1.0f, 0.0f);
#pragma unroll
    for (int j = 1; j < 8; j++) t.m[j] = cmul(t.m[j - 1], mb);
}

__device__ __forceinline__ void fft_fwd(float2 d[8], const FTw& t, int lane) {
#pragma unroll
    for (int s = 0; s < 5; s++) {
        int S = 16 >> s;
        float2 w = t.ws[s];
        bool hi = (lane & S) != 0;
#pragma unroll
        for (int j = 0; j < 8; j++) {
            float2 o = shflxc(d[j], S);
            d[j] = hi ? cmul(csub(o, d[j]), w) : cadd(d[j], o);
        }
    }
#pragma unroll
    for (int j = 1; j < 8; j++) d[j] = cmul(d[j], t.m[j]);
    const float R = 0.70710678118654752f;
    const float2 W81 = make_float2(R, -R);
    const float2 W83 = make_float2(-R, -R);
    {
        float2 u, v, tt;
        u = d[0]; v = d[4]; d[0] = cadd(u, v); d[4] = csub(u, v);
        u = d[1]; v = d[5]; d[1] = cadd(u, v); d[5] = cmul(csub(u, v), W81);
        u = d[2]; v = d[6]; d[2] = cadd(u, v); tt = csub(u, v); d[6] = make_float2(tt.y, -tt.x);
        u = d[3]; v = d[7]; d[3] = cadd(u, v); d[7] = cmul(csub(u, v), W83);
    }
#pragma unroll
    for (int gg = 0; gg < 8; gg += 4) {
        float2 u, v, tt;
        u = d[gg];     v = d[gg + 2]; d[gg] = cadd(u, v);     d[gg + 2] = csub(u, v);
        u = d[gg + 1]; v = d[gg + 3]; tt = csub(u, v);
        d[gg + 1] = cadd(u, v); d[gg + 3] = make_float2(tt.y, -tt.x);
    }
#pragma unroll
    for (int gg = 0; gg < 8; gg += 2) {
        float2 u = d[gg], v = d[gg + 1];
        d[gg] = cadd(u, v); d[gg + 1] = csub(u, v);
    }
}

__device__ __forceinline__ void fft_inv(float2 d[8], const FTw& t, int lane) {
    const float R = 0.70710678118654752f;
    const float2 W81c = make_float2(R, R);
    const float2 W83c = make_float2(-R, R);
#pragma unroll
    for (int gg = 0; gg < 8; gg += 2) {
        float2 a = d[gg], b = d[gg + 1];
        d[gg] = cadd(a, b); d[gg + 1] = csub(a, b);
    }
#pragma unroll
    for (int gg = 0; gg < 8; gg += 4) {
        float2 a, b, vb;
        a = d[gg];     b = d[gg + 2]; d[gg] = cadd(a, b); d[gg + 2] = csub(a, b);
        a = d[gg + 1]; b = d[gg + 3]; vb = make_float2(-b.y, b.x);
        d[gg + 1] = cadd(a, vb); d[gg + 3] = csub(a, vb);
    }
    {
        float2 a, v;
        a = d[0]; v = d[4];                d[0] = cadd(a, v); d[4] = csub(a, v);
        a = d[1]; v = cmul(d[5], W81c);    d[1] = cadd(a, v); d[5] = csub(a, v);
        a = d[2]; { float2 bq = d[6]; v = make_float2(-bq.y, bq.x); } d[2] = cadd(a, v); d[6] = csub(a, v);
        a = d[3]; v = cmul(d[7], W83c);    d[3] = cadd(a, v); d[7] = csub(a, v);
    }
#pragma unroll
    for (int j = 1; j < 8; j++) {
        float2 mc = make_float2(t.m[j].x, -t.m[j].y);
        d[j] = cmul(d[j], mc);
    }
#pragma unroll
    for (int s = 0; s < 5; s++) {
        int S = 1 << s;
        float2 w = t.ws[4 - s];
        float2 wc = make_float2(w.x, -w.y);
        bool hi = (lane & S) != 0;
#pragma unroll
        for (int j = 0; j < 8; j++) {
            float2 pre = hi ? cmul(d[j], wc) : d[j];
            float2 o = shflxc(pre, S);
            d[j] = hi ? csub(o, pre) : cadd(pre, o);
        }
    }
}

__device__ __forceinline__ void apply_mask(float2 d[8]) {
    d[1] = make_float2(0.f, 0.f);
    d[2] = make_float2(0.f, 0.f);
    d[5] = make_float2(0.f, 0.f);
    d[6] = make_float2(0.f, 0.f);
}

__global__ void __launch_bounds__(256) row_kernel() {
    int lane = threadIdx.x & 31;
    int wp = threadIdx.x >> 5;
    FTw t;
    make_tw(lane, t);
    int base = (blockIdx.x * 8 + wp) * 16;
    const float sc = 1.0f / 256.0f;
    for (int i = 0; i < 16; i++) {
        int row = base + i;
        const float4* yr = (const float4*)(g_y + (size_t)row * 256);
        float4 a = yr[lane * 2 + 0];
        float4 bq = yr[lane * 2 + 1];
        float2 d[8];
        d[0] = make_float2(a.x, 0.f);  d[1] = make_float2(a.y, 0.f);
        d[2] = make_float2(a.z, 0.f);  d[3] = make_float2(a.w, 0.f);
        d[4] = make_float2(bq.x, 0.f); d[5] = make_float2(bq.y, 0.f);
        d[6] = make_float2(bq.z, 0.f); d[7] = make_float2(bq.w, 0.f);
        fft_fwd(d, t, lane);
        apply_mask(d);
        fft_inv(d, t, lane);
        float4* ur = (float4*)(g_u4 + (size_t)row * 128);
        ur[lane * 4 + 0] = make_float4(d[0].x * sc, d[0].y * sc, d[1].x * sc, d[1].y * sc);
        ur[lane * 4 + 1] = make_float4(d[2].x * sc, d[2].y * sc, d[3].x * sc, d[3].y * sc);
        ur[lane * 4 + 2] = make_float4(d[4].x * sc, d[4].y * sc, d[5].x * sc, d[5].y * sc);
        ur[lane * 4 + 3] = make_float4(d[6].x * sc, d[6].y * sc, d[7].x * sc, d[7].y * sc);
    }
}

__global__ void __launch_bounds__(256) col_kernel(const float* __restrict__ beta,
                                                  float* __restrict__ out) {
    __shared__ float2 tile[16][257];
    int t = threadIdx.x;
    int img = blockIdx.x >> 4;
    int c0 = (blockIdx.x & 15) << 4;
    size_t ibase = (size_t)img * 65536;
    const float2* u2 = (const float2*)g_u4;

    int cL = t & 15;
    int rg = t >> 4;
    for (int k = 0; k < 16; k++) {
        int r = rg + k * 16;
        tile[cL][((r & 7) << 5) | (r >> 3)] = u2[ibase + (size_t)r * 256 + c0 + cL];
    }
    __syncthreads();

    int lane = t & 31;
    int wp = t >> 5;
    FTw tw;
    make_tw(lane, tw);
    const float sc = 1.0f / 256.0f;
    for (int cc = 0; cc < 2; cc++) {
        int cl = wp + cc * 8;
        float2 d[8];
#pragma unroll
        for (int j = 0; j < 8; j++) d[j] = tile[cl][j * 32 + lane];
        fft_fwd(d, tw, lane);
        apply_mask(d);
        fft_inv(d, tw, lane);
#pragma unroll
        for (int j = 0; j < 8; j++) {
            float vx = d[j].x * sc, vy = d[j].y * sc;
            tile[cl][j * 32 + lane].x = sqrtf(vx * vx + vy * vy);
        }
    }
    __syncthreads();

    float be = *beta;
    float a0 = be;
    float a1 = 1.0f - 2.0f * be;
    for (int k = 0; k < 16; k++) {
        int idx = k * 256 + t;
        int r = idx >> 4;
        int c = idx & 15;
        size_t gg = ibase + (size_t)r * 256 + c0 + c;
        out[gg] = a0 * g_y[gg] + a1 * tile[c][((r & 7) << 5) | (r >> 3)].x;
    }
}

// ---------------------------------------------------------------------------
extern "C" void kernel_launch(void* const* d_in, const int* in_sizes, int n_in,
                              void* d_out, int out_size) {
    const float* x = (const float*)d_in[0];
    const float* w = (const float*)d_in[1];
    const float* beta = (const float*)d_in[2];
    float* out = (float*)d_out;

    cudaFuncSetAttribute(conv_mma_kernel, cudaFuncAttributeMaxDynamicSharedMemorySize, CONV_SMEM);

    wprep_kernel<<<972, 256>>>(w);
    xprep_kernel<<<dim3(512, 3, 8), 256>>>(x);
    conv_mma_kernel<<<dim3(128, 8), 256, CONV_SMEM>>>();
    row_kernel<<<768, 256>>>();
    col_kernel<<<384 * 16, 256>>>(beta, out);
}

// round 4
// speedup vs baseline: 2.6890x; 1.1867x over previous
#include <cuda_runtime.h>
#include <cuda_fp16.h>
#include <math.h>
#include <stdint.h>

#define PI_F 3.14159265358979f

// ---------------------------------------------------------------------------
// Scratch (__device__ globals; no runtime alloc)
// ---------------------------------------------------------------------------
__device__ float  g_y[25165824];          // conv output, pixel-shuffled (8,48,256,256)
__device__ float4 g_u4[25165824 / 2];     // row-filtered complex field
__device__ __half g_xh[12582912];         // x transposed [b][hw][ic], fp16 hi
__device__ __half g_xl[12582912];         // fp16 residual (x = xh + xl to ~2^-22)
__device__ __half g_wimg[248832];         // weights fp16: 54 chunks x [192 oc][24 k]

// ---------------------------------------------------------------------------
// mma.sync (fp16 in, f32 acc) — baseline PTX feature, valid at compute_103
// ---------------------------------------------------------------------------
__device__ __forceinline__ void mma16816(float c[4],
                                         uint32_t a0, uint32_t a1, uint32_t a2, uint32_t a3,
                                         uint32_t b0, uint32_t b1) {
    asm volatile(
        "mma.sync.aligned.m16n8k16.row.col.f32.f16.f16.f32 "
        "{%0,%1,%2,%3}, {%4,%5,%6,%7}, {%8,%9}, {%0,%1,%2,%3};"
        : "+f"(c[0]), "+f"(c[1]), "+f"(c[2]), "+f"(c[3])
        : "r"(a0), "r"(a1), "r"(a2), "r"(a3), "r"(b0), "r"(b1));
}

__device__ __forceinline__ uint32_t smem_u32(const void* p) {
    uint32_t a;
    asm("{ .reg .u64 t; cvta.to.shared.u64 t, %1; cvt.u32.u64 %0, t; }" : "=r"(a) : "l"(p));
    return a;
}
__device__ __forceinline__ void cp_async16(uint32_t dst, const void* src) {
    asm volatile("cp.async.cg.shared.global [%0], [%1], 16;" :: "r"(dst), "l"(src));
}
__device__ __forceinline__ void cp_commit() { asm volatile("cp.async.commit_group;"); }
__device__ __forceinline__ void cp_wait0()  { asm volatile("cp.async.wait_group 0;"); }

// ---------------------------------------------------------------------------
// Warp-FFT machinery (proven rounds 1-3)
// ---------------------------------------------------------------------------
__device__ __forceinline__ float2 cadd(float2 a, float2 b) { return make_float2(a.x + b.x, a.y + b.y); }
__device__ __forceinline__ float2 csub(float2 a, float2 b) { return make_float2(a.x - b.x, a.y - b.y); }
__device__ __forceinline__ float2 cmul(float2 a, float2 b) {
    return make_float2(a.x * b.x - a.y * b.y, a.x * b.y + a.y * b.x);
}
__device__ __forceinline__ float2 expi(float a) { return make_float2(cosf(a), sinf(a)); }
__device__ __forceinline__ float2 shflxc(float2 v, int m) {
    v.x = __shfl_xor_sync(0xffffffffu, v.x, m);
    v.y = __shfl_xor_sync(0xffffffffu, v.y, m);
    return v;
}

struct FTw { float2 ws[5]; float2 m[8]; };

__device__ __forceinline__ void make_tw(int lane, FTw& t) {
    int brl = __brev((unsigned)lane) >> 27;
    t.ws[0] = expi(-PI_F * (float)(lane & 15) / 16.0f);
    t.ws[1] = expi(-PI_F * (float)(lane & 7) / 8.0f);
    t.ws[2] = expi(-PI_F * (float)(lane & 3) / 4.0f);
    t.ws[3] = expi(-PI_F * (float)(lane & 1) / 2.0f);
    t.ws[4] = make_float2(1.0f, 0.0f);
    float2 mb = expi(-2.0f * PI_F * (float)brl / 256.0f);
    t.m[0] = make_float2(1.0f, 0.0f);
#pragma unroll
    for (int j = 1; j < 8; j++) t.m[j] = cmul(t.m[j - 1], mb);
}

__device__ __forceinline__ void fft_fwd(float2 d[8], const FTw& t, int lane) {
#pragma unroll
    for (int s = 0; s < 5; s++) {
        int S = 16 >> s;
        float2 w = t.ws[s];
        bool hi = (lane & S) != 0;
#pragma unroll
        for (int j = 0; j < 8; j++) {
            float2 o = shflxc(d[j], S);
            d[j] = hi ? cmul(csub(o, d[j]), w) : cadd(d[j], o);
        }
    }
#pragma unroll
    for (int j = 1; j < 8; j++) d[j] = cmul(d[j], t.m[j]);
    const float R = 0.70710678118654752f;
    const float2 W81 = make_float2(R, -R);
    const float2 W83 = make_float2(-R, -R);
    {
        float2 u, v, tt;
        u = d[0]; v = d[4]; d[0] = cadd(u, v); d[4] = csub(u, v);
        u = d[1]; v = d[5]; d[1] = cadd(u, v); d[5] = cmul(csub(u, v), W81);
        u = d[2]; v = d[6]; d[2] = cadd(u, v); tt = csub(u, v); d[6] = make_float2(tt.y, -tt.x);
        u = d[3]; v = d[7]; d[3] = cadd(u, v); d[7] = cmul(csub(u, v), W83);
    }
#pragma unroll
    for (int gg = 0; gg < 8; gg += 4) {
        float2 u, v, tt;
        u = d[gg];     v = d[gg + 2]; d[gg] = cadd(u, v);     d[gg + 2] = csub(u, v);
        u = d[gg + 1]; v = d[gg + 3]; tt = csub(u, v);
        d[gg + 1] = cadd(u, v); d[gg + 3] = make_float2(tt.y, -tt.x);
    }
#pragma unroll
    for (int gg = 0; gg < 8; gg += 2) {
        float2 u = d[gg], v = d[gg + 1];
        d[gg] = cadd(u, v); d[gg + 1] = csub(u, v);
    }
}

__device__ __forceinline__ void fft_inv(float2 d[8], const FTw& t, int lane) {
    const float R = 0.70710678118654752f;
    const float2 W81c = make_float2(R, R);
    const float2 W83c = make_float2(-R, R);
#pragma unroll
    for (int gg = 0; gg < 8; gg += 2) {
        float2 a = d[gg], b = d[gg + 1];
        d[gg] = cadd(a, b); d[gg + 1] = csub(a, b);
    }
#pragma unroll
    for (int gg = 0; gg < 8; gg += 4) {
        float2 a, b, vb;
        a = d[gg];     b = d[gg + 2]; d[gg] = cadd(a, b); d[gg + 2] = csub(a, b);
        a = d[gg + 1]; b = d[gg + 3]; vb = make_float2(-b.y, b.x);
        d[gg + 1] = cadd(a, vb); d[gg + 3] = csub(a, vb);
    }
    {
        float2 a, v;
        a = d[0]; v = d[4];                d[0] = cadd(a, v); d[4] = csub(a, v);
        a = d[1]; v = cmul(d[5], W81c);    d[1] = cadd(a, v); d[5] = csub(a, v);
        a = d[2]; { float2 bq = d[6]; v = make_float2(-bq.y, bq.x); } d[2] = cadd(a, v); d[6] = csub(a, v);
        a = d[3]; v = cmul(d[7], W83c);    d[3] = cadd(a, v); d[7] = csub(a, v);
    }
#pragma unroll
    for (int j = 1; j < 8; j++) {
        float2 mc = make_float2(t.m[j].x, -t.m[j].y);
        d[j] = cmul(d[j], mc);
    }
#pragma unroll
    for (int s = 0; s < 5; s++) {
        int S = 1 << s;
        float2 w = t.ws[4 - s];
        float2 wc = make_float2(w.x, -w.y);
        bool hi = (lane & S) != 0;
#pragma unroll
        for (int j = 0; j < 8; j++) {
            float2 pre = hi ? cmul(d[j], wc) : d[j];
            float2 o = shflxc(pre, S);
            d[j] = hi ? csub(o, pre) : cadd(pre, o);
        }
    }
}

__device__ __forceinline__ void apply_mask(float2 d[8]) {
    d[1] = make_float2(0.f, 0.f);
    d[2] = make_float2(0.f, 0.f);
    d[5] = make_float2(0.f, 0.f);
    d[6] = make_float2(0.f, 0.f);
}

// ---------------------------------------------------------------------------
// Prep 1: weights -> single fp16 image per k16 chunk.
// chunk c = tap*6 + icg; layout: wimg[c*4608 + oc*24 + j], j<16 valid.
// ---------------------------------------------------------------------------
__global__ void wprep_kernel(const float* __restrict__ wgt) {
    int i = blockIdx.x * 256 + threadIdx.x;
    if (i >= 248832) return;
    int j = i % 24;
    int oc = (i / 24) % 192;
    int c = i / (24 * 192);
    int tap = c / 6, icg = c % 6;
    int kh = tap / 3, kw = tap % 3;
    float w = 0.0f;
    if (j < 16) {
        int ic = icg * 16 + j;
        w = wgt[((size_t)oc * 96 + ic) * 9 + kh * 3 + kw];
    }
    g_wimg[c * 4608 + oc * 24 + j] = __float2half(w);
}

// ---------------------------------------------------------------------------
// Prep 2: transpose x (b,ic,h,w) f32 -> (b, hw, ic) fp16 hi + residual lo.
// ---------------------------------------------------------------------------
__global__ void __launch_bounds__(256) xprep_kernel(const float* __restrict__ x) {
    __shared__ float tile[32][33];
    int t = threadIdx.x;
    int j = t & 31, i4 = t >> 5;
    int hw0 = blockIdx.x * 32;
    int ic0 = blockIdx.y * 32;
    int b = blockIdx.z;
#pragma unroll
    for (int r = 0; r < 4; r++) {
        int ic = ic0 + i4 * 4 + r;
        tile[i4 * 4 + r][j] = x[((size_t)b * 96 + ic) * 16384 + hw0 + j];
    }
    __syncthreads();
#pragma unroll
    for (int r = 0; r < 4; r++) {
        int hwl = i4 * 4 + r;
        float v = tile[j][hwl];
        __half hi = __float2half(v);
        __half lo = __float2half(v - __half2float(hi));
        size_t idx = ((size_t)b * 16384 + hw0 + hwl) * 96 + ic0 + j;
        g_xh[idx] = hi;
        g_xl[idx] = lo;
    }
}

// ---------------------------------------------------------------------------
// Conv via mma.sync implicit GEMM + FUSED row-FFT epilogue.
// CTA = (h, b): D[192 oc][128 px], K=864 in 54 k16 chunks, 2 products
// (xh*w + xl*w = x*w exactly; w already fp16).
// Epilogue: stage D pixel-shuffled in smem [96 rows][264], each warp FFTs
// 12 rows -> writes g_y (coalesced) and g_u.
// ---------------------------------------------------------------------------
#define XS_ELEMS 40560              // 3*130*104 fp16 per copy
#define WSLOT_OFF_B 162240          // bytes: 2 copies * XS_ELEMS * 2B
#define SLOT_BYTES 9216             // 4608 fp16
#define CONV_SMEM (WSLOT_OFF_B + 2 * SLOT_BYTES)
#define STG_STRIDE 264

__global__ void __launch_bounds__(256) conv_mma_kernel() {
    extern __shared__ char sd[];
    __half* xsH = (__half*)sd;
    __half* xsL = xsH + XS_ELEMS;
    __half* wring = (__half*)(sd + WSLOT_OFF_B);

    int t = threadIdx.x;
    int h = blockIdx.x;
    int b = blockIdx.y;
    int wid = t >> 5, lane = t & 31;
    int g = lane >> 2, tig = lane & 3;
    int ocbase = (wid >> 2) * 96;
    int pxbase = (wid & 3) * 32;

    // Preload chunk 0 weights (576 x 16B)
    uint32_t wring_s = smem_u32(wring);
    for (int i = t; i < 576; i += 256)
        cp_async16(wring_s + i * 16, (const char*)g_wimg + i * 16);
    cp_commit();

    // Stage input rows (hi & lo) with halo: [3 kh][130 ww][104 ic]
    {
        const __half* xb_h = g_xh + (size_t)b * 16384 * 96;
        const __half* xb_l = g_xl + (size_t)b * 16384 * 96;
        for (int idx = t; idx < 4680; idx += 256) {
            int c16 = idx % 12;
            int ww = (idx / 12) % 130;
            int kh = idx / (12 * 130);
            int hp = h + kh - 1;
            int wp = ww - 1;
            uint4 vh = make_uint4(0, 0, 0, 0), vl = vh;
            if (hp >= 0 && hp < 128 && wp >= 0 && wp < 128) {
                size_t src = ((size_t)hp * 128 + wp) * 96 + c16 * 8;
                vh = *(const uint4*)(xb_h + src);
                vl = *(const uint4*)(xb_l + src);
            }
            int dst = kh * 13520 + ww * 104 + c16 * 8;
            *(uint4*)(xsH + dst) = vh;
            *(uint4*)(xsL + dst) = vl;
        }
    }
    cp_wait0();
    __syncthreads();

    float acc[6][4][4];
#pragma unroll
    for (int m = 0; m < 6; m++)
#pragma unroll
        for (int n = 0; n < 4; n++)
#pragma unroll
            for (int q = 0; q < 4; q++) acc[m][n][q] = 0.0f;

    for (int c = 0; c < 54; c++) {
        if (c < 53) {
            uint32_t dsts = wring_s + ((c + 1) & 1) * SLOT_BYTES;
            const char* srcg = (const char*)g_wimg + (size_t)(c + 1) * SLOT_BYTES;
            for (int i = t; i < 576; i += 256)
                cp_async16(dsts + i * 16, srcg + i * 16);
            cp_commit();
        }

        int tap = c / 6, icg = c % 6;
        int kh = tap / 3, kw = tap % 3;
        const __half* wslot = wring + (c & 1) * 4608;

        // B fragments (input x), hi & lo copies
        uint32_t bh0[4], bh1[4], bl0[4], bl1[4];
        int rowb = kh * 130 + pxbase + kw + g;
        int icoff = icg * 16 + 2 * tig;
#pragma unroll
        for (int n = 0; n < 4; n++) {
            int off = (rowb + n * 8) * 104 + icoff;
            bh0[n] = *(const uint32_t*)(xsH + off);
            bh1[n] = *(const uint32_t*)(xsH + off + 8);
            bl0[n] = *(const uint32_t*)(xsL + off);
            bl1[n] = *(const uint32_t*)(xsL + off + 8);
        }
#pragma unroll
        for (int m = 0; m < 6; m++) {
            const __half* pA = wslot + (ocbase + m * 16 + g) * 24 + 2 * tig;
            uint32_t a0 = *(const uint32_t*)pA;
            uint32_t a1 = *(const uint32_t*)(pA + 192);
            uint32_t a2 = *(const uint32_t*)(pA + 8);
            uint32_t a3 = *(const uint32_t*)(pA + 200);
#pragma unroll
            for (int n = 0; n < 4; n++) {
                mma16816(acc[m][n], a0, a1, a2, a3, bh0[n], bh1[n]);
                mma16816(acc[m][n], a0, a1, a2, a3, bl0[n], bl1[n]);
            }
        }
        if (c < 53) cp_wait0();
        __syncthreads();
    }

    // ---- Fused epilogue: stage pixel-shuffled D, then per-warp row FFT ----
    float* stage = (float*)sd;   // 96 rows x 264 f32 = 101376 B (xs region, done)
#pragma unroll
    for (int m = 0; m < 6; m++) {
#pragma unroll
        for (int n = 0; n < 4; n++) {
#pragma unroll
            for (int q = 0; q < 4; q++) {
                int oc = ocbase + m * 16 + g + 8 * (q >> 1);
                int px = pxbase + n * 8 + 2 * tig + (q & 1);
                int r2 = oc >> 1;                 // cch*2 + pbit
                int col = 2 * px + (oc & 1);
                stage[r2 * STG_STRIDE + col] = acc[m][n][q];
            }
        }
    }
    __syncthreads();

    FTw tw;
    make_tw(lane, tw);
    const float sc = 1.0f / 256.0f;
#pragma unroll 1
    for (int rr = 0; rr < 12; rr++) {
        int r2 = wid * 12 + rr;
        const float* rowp = stage + r2 * STG_STRIDE;
        float4 v0 = *(const float4*)(rowp + 8 * lane);
        float4 v1 = *(const float4*)(rowp + 8 * lane + 4);
        size_t grow = ((size_t)b * 48 + (r2 >> 1)) * 256 + 2 * h + (r2 & 1);
        float4* yrow = (float4*)(g_y + grow * 256);
        yrow[2 * lane] = v0;
        yrow[2 * lane + 1] = v1;
        float2 d[8];
        d[0] = make_float2(v0.x, 0.f); d[1] = make_float2(v0.y, 0.f);
        d[2] = make_float2(v0.z, 0.f); d[3] = make_float2(v0.w, 0.f);
        d[4] = make_float2(v1.x, 0.f); d[5] = make_float2(v1.y, 0.f);
        d[6] = make_float2(v1.z, 0.f); d[7] = make_float2(v1.w, 0.f);
        fft_fwd(d, tw, lane);
        apply_mask(d);
        fft_inv(d, tw, lane);
        float4* ur = (float4*)(g_u4 + grow * 128);
        ur[lane * 4 + 0] = make_float4(d[0].x * sc, d[0].y * sc, d[1].x * sc, d[1].y * sc);
        ur[lane * 4 + 1] = make_float4(d[2].x * sc, d[2].y * sc, d[3].x * sc, d[3].y * sc);
        ur[lane * 4 + 2] = make_float4(d[4].x * sc, d[4].y * sc, d[5].x * sc, d[5].y * sc);
        ur[lane * 4 + 3] = make_float4(d[6].x * sc, d[6].y * sc, d[7].x * sc, d[7].y * sc);
    }
}

// ---------------------------------------------------------------------------
// Column pass + magnitude + combine (unchanged)
// ---------------------------------------------------------------------------
__global__ void __launch_bounds__(256) col_kernel(const float* __restrict__ beta,
                                                  float* __restrict__ out) {
    __shared__ float2 tile[16][257];
    int t = threadIdx.x;
    int img = blockIdx.x >> 4;
    int c0 = (blockIdx.x & 15) << 4;
    size_t ibase = (size_t)img * 65536;
    const float2* u2 = (const float2*)g_u4;

    int cL = t & 15;
    int rg = t >> 4;
    for (int k = 0; k < 16; k++) {
        int r = rg + k * 16;
        tile[cL][((r & 7) << 5) | (r >> 3)] = u2[ibase + (size_t)r * 256 + c0 + cL];
    }
    __syncthreads();

    int lane = t & 31;
    int wp = t >> 5;
    FTw tw;
    make_tw(lane, tw);
    const float sc = 1.0f / 256.0f;
    for (int cc = 0; cc < 2; cc++) {
        int cl = wp + cc * 8;
        float2 d[8];
#pragma unroll
        for (int j = 0; j < 8; j++) d[j] = tile[cl][j * 32 + lane];
        fft_fwd(d, tw, lane);
        apply_mask(d);
        fft_inv(d, tw, lane);
#pragma unroll
        for (int j = 0; j < 8; j++) {
            float vx = d[j].x * sc, vy = d[j].y * sc;
            tile[cl][j * 32 + lane].x = sqrtf(vx * vx + vy * vy);
        }
    }
    __syncthreads();

    float be = *beta;
    float a0 = be;
    float a1 = 1.0f - 2.0f * be;
    for (int k = 0; k < 16; k++) {
        int idx = k * 256 + t;
        int r = idx >> 4;
        int c = idx & 15;
        size_t gg = ibase + (size_t)r * 256 + c0 + c;
        out[gg] = a0 * g_y[gg] + a1 * tile[c][((r & 7) << 5) | (r >> 3)].x;
    }
}

// ---------------------------------------------------------------------------
extern "C" void kernel_launch(void* const* d_in, const int* in_sizes, int n_in,
                              void* d_out, int out_size) {
    const float* x = (const float*)d_in[0];
    const float* w = (const float*)d_in[1];
    const float* beta = (const float*)d_in[2];
    float* out = (float*)d_out;

    cudaFuncSetAttribute(conv_mma_kernel, cudaFuncAttributeMaxDynamicSharedMemorySize, CONV_SMEM);

    wprep_kernel<<<972, 256>>>(w);
    xprep_kernel<<<dim3(512, 3, 8), 256>>>(x);
    conv_mma_kernel<<<dim3(128, 8), 256, CONV_SMEM>>>();
    col_kernel<<<384 * 16, 256>>>(beta, out);
}

// round 6
// speedup vs baseline: 2.8695x; 1.0671x over previous
#include <cuda_runtime.h>
#include <cuda_fp16.h>
#include <math.h>
#include <stdint.h>

#define PI_F 3.14159265358979f

// ---------------------------------------------------------------------------
// Scratch (__device__ globals; no runtime alloc)
// ---------------------------------------------------------------------------
__device__ __half    g_yh[25165824];      // conv output fp16, pixel-shuffled (8,48,256,256)
__device__ uint32_t  g_uh[25165824];      // row-filtered complex field, half2 (re,im) per pixel
__device__ __half    g_xh[12582912];      // x transposed [b][hw][ic], fp16 hi
__device__ __half    g_xl[12582912];      // fp16 residual (x = xh + xl to ~2^-22)
__device__ __half    g_wimg[248832];      // weights fp16: 54 chunks x [192 oc][24 k]

// ---------------------------------------------------------------------------
// mma.sync (fp16 in, f32 acc)
// ---------------------------------------------------------------------------
__device__ __forceinline__ void mma16816(float c[4],
                                         uint32_t a0, uint32_t a1, uint32_t a2, uint32_t a3,
                                         uint32_t b0, uint32_t b1) {
    asm volatile(
        "mma.sync.aligned.m16n8k16.row.col.f32.f16.f16.f32 "
        "{%0,%1,%2,%3}, {%4,%5,%6,%7}, {%8,%9}, {%0,%1,%2,%3};"
        : "+f"(c[0]), "+f"(c[1]), "+f"(c[2]), "+f"(c[3])
        : "r"(a0), "r"(a1), "r"(a2), "r"(a3), "r"(b0), "r"(b1));
}

__device__ __forceinline__ uint32_t smem_u32(const void* p) {
    uint32_t a;
    asm("{ .reg .u64 t; cvta.to.shared.u64 t, %1; cvt.u32.u64 %0, t; }" : "=r"(a) : "l"(p));
    return a;
}
__device__ __forceinline__ void cp_async16(uint32_t dst, const void* src) {
    asm volatile("cp.async.cg.shared.global [%0], [%1], 16;" :: "r"(dst), "l"(src));
}
__device__ __forceinline__ void cp_commit() { asm volatile("cp.async.commit_group;"); }
__device__ __forceinline__ void cp_wait0()  { asm volatile("cp.async.wait_group 0;"); }

// pack two floats -> half2 (lo = a, hi = b)
__device__ __forceinline__ uint32_t pack_h2(float a, float b) {
    uint32_t r;
    asm("cvt.rn.f16x2.f32 %0, %1, %2;" : "=r"(r) : "f"(b), "f"(a));
    return r;
}
__device__ __forceinline__ float2 unpack_h2(uint32_t v) {
    __half2 h = *reinterpret_cast<const __half2*>(&v);
    return __half22float2(h);
}

// ---------------------------------------------------------------------------
// Warp-FFT machinery (fast twiddles via __sincosf; err ~1e-6, negligible)
// ---------------------------------------------------------------------------
__device__ __forceinline__ float2 cadd(float2 a, float2 b) { return make_float2(a.x + b.x, a.y + b.y); }
__device__ __forceinline__ float2 csub(float2 a, float2 b) { return make_float2(a.x - b.x, a.y - b.y); }
__device__ __forceinline__ float2 cmul(float2 a, float2 b) {
    return make_float2(a.x * b.x - a.y * b.y, a.x * b.y + a.y * b.x);
}
__device__ __forceinline__ float2 expi(float a) {
    float s, c;
    __sincosf(a, &s, &c);
    return make_float2(c, s);
}
__device__ __forceinline__ float2 shflxc(float2 v, int m) {
    v.x = __shfl_xor_sync(0xffffffffu, v.x, m);
    v.y = __shfl_xor_sync(0xffffffffu, v.y, m);
    return v;
}

struct FTw { float2 ws[5]; float2 m[8]; };

__device__ __forceinline__ void make_tw(int lane, FTw& t) {
    int brl = __brev((unsigned)lane) >> 27;
    t.ws[0] = expi(-PI_F * (float)(lane & 15) / 16.0f);
    t.ws[1] = expi(-PI_F * (float)(lane & 7) / 8.0f);
    t.ws[2] = expi(-PI_F * (float)(lane & 3) / 4.0f);
    t.ws[3] = expi(-PI_F * (float)(lane & 1) / 2.0f);
    t.ws[4] = make_float2(1.0f, 0.0f);
    float2 mb = expi(-2.0f * PI_F * (float)brl / 256.0f);
    t.m[0] = make_float2(1.0f, 0.0f);
#pragma unroll
    for (int j = 1; j < 8; j++) t.m[j] = cmul(t.m[j - 1], mb);
}

__device__ __forceinline__ void fft_fwd(float2 d[8], const FTw& t, int lane) {
#pragma unroll
    for (int s = 0; s < 5; s++) {
        int S = 16 >> s;
        float2 w = t.ws[s];
        bool hi = (lane & S) != 0;
#pragma unroll
        for (int j = 0; j < 8; j++) {
            float2 o = shflxc(d[j], S);
            d[j] = hi ? cmul(csub(o, d[j]), w) : cadd(d[j], o);
        }
    }
#pragma unroll
    for (int j = 1; j < 8; j++) d[j] = cmul(d[j], t.m[j]);
    const float R = 0.70710678118654752f;
    const float2 W81 = make_float2(R, -R);
    const float2 W83 = make_float2(-R, -R);
    {
        float2 u, v, tt;
        u = d[0]; v = d[4]; d[0] = cadd(u, v); d[4] = csub(u, v);
        u = d[1]; v = d[5]; d[1] = cadd(u, v); d[5] = cmul(csub(u, v), W81);
        u = d[2]; v = d[6]; d[2] = cadd(u, v); tt = csub(u, v); d[6] = make_float2(tt.y, -tt.x);
        u = d[3]; v = d[7]; d[3] = cadd(u, v); d[7] = cmul(csub(u, v), W83);
    }
#pragma unroll
    for (int gg = 0; gg < 8; gg += 4) {
        float2 u, v, tt;
        u = d[gg];     v = d[gg + 2]; d[gg] = cadd(u, v);     d[gg + 2] = csub(u, v);
        u = d[gg + 1]; v = d[gg + 3]; tt = csub(u, v);
        d[gg + 1] = cadd(u, v); d[gg + 3] = make_float2(tt.y, -tt.x);
    }
#pragma unroll
    for (int gg = 0; gg < 8; gg += 2) {
        float2 u = d[gg], v = d[gg + 1];
        d[gg] = cadd(u, v); d[gg + 1] = csub(u, v);
    }
}

__device__ __forceinline__ void fft_inv(float2 d[8], const FTw& t, int lane) {
    const float R = 0.70710678118654752f;
    const float2 W81c = make_float2(R, R);
    const float2 W83c = make_float2(-R, R);
#pragma unroll
    for (int gg = 0; gg < 8; gg += 2) {
        float2 a = d[gg], b = d[gg + 1];
        d[gg] = cadd(a, b); d[gg + 1] = csub(a, b);
    }
#pragma unroll
    for (int gg = 0; gg < 8; gg += 4) {
        float2 a, b, vb;
        a = d[gg];     b = d[gg + 2]; d[gg] = cadd(a, b); d[gg + 2] = csub(a, b);
        a = d[gg + 1]; b = d[gg + 3]; vb = make_float2(-b.y, b.x);
        d[gg + 1] = cadd(a, vb); d[gg + 3] = csub(a, vb);
    }
    {
        float2 a, v;
        a = d[0]; v = d[4];                d[0] = cadd(a, v); d[4] = csub(a, v);
        a = d[1]; v = cmul(d[5], W81c);    d[1] = cadd(a, v); d[5] = csub(a, v);
        a = d[2]; { float2 bq = d[6]; v = make_float2(-bq.y, bq.x); } d[2] = cadd(a, v); d[6] = csub(a, v);
        a = d[3]; v = cmul(d[7], W83c);    d[3] = cadd(a, v); d[7] = csub(a, v);
    }
#pragma unroll
    for (int j = 1; j < 8; j++) {
        float2 mc = make_float2(t.m[j].x, -t.m[j].y);
        d[j] = cmul(d[j], mc);
    }
#pragma unroll
    for (int s = 0; s < 5; s++) {
        int S = 1 << s;
        float2 w = t.ws[4 - s];
        float2 wc = make_float2(w.x, -w.y);
        bool hi = (lane & S) != 0;
#pragma unroll
        for (int j = 0; j < 8; j++) {
            float2 pre = hi ? cmul(d[j], wc) : d[j];
            float2 o = shflxc(pre, S);
            d[j] = hi ? csub(o, pre) : cadd(pre, o);
        }
    }
}

__device__ __forceinline__ void apply_mask(float2 d[8]) {
    d[1] = make_float2(0.f, 0.f);
    d[2] = make_float2(0.f, 0.f);
    d[5] = make_float2(0.f, 0.f);
    d[6] = make_float2(0.f, 0.f);
}

// ---------------------------------------------------------------------------
// Prep 1: weights -> fp16 image per k16 chunk: wimg[c*4608 + oc*24 + j]
// ---------------------------------------------------------------------------
__global__ void wprep_kernel(const float* __restrict__ wgt) {
    int i = blockIdx.x * 256 + threadIdx.x;
    if (i >= 248832) return;
    int j = i % 24;
    int oc = (i / 24) % 192;
    int c = i / (24 * 192);
    int tap = c / 6, icg = c % 6;
    int kh = tap / 3, kw = tap % 3;
    float w = 0.0f;
    if (j < 16) {
        int ic = icg * 16 + j;
        w = wgt[((size_t)oc * 96 + ic) * 9 + kh * 3 + kw];
    }
    g_wimg[c * 4608 + oc * 24 + j] = __float2half(w);
}

// ---------------------------------------------------------------------------
// Prep 2: transpose x (b,ic,h,w) f32 -> (b, hw, ic) fp16 hi + residual lo.
// ---------------------------------------------------------------------------
__global__ void __launch_bounds__(256) xprep_kernel(const float* __restrict__ x) {
    __shared__ float tile[32][33];
    int t = threadIdx.x;
    int j = t & 31, i4 = t >> 5;
    int hw0 = blockIdx.x * 32;
    int ic0 = blockIdx.y * 32;
    int b = blockIdx.z;
#pragma unroll
    for (int r = 0; r < 4; r++) {
        int ic = ic0 + i4 * 4 + r;
        tile[i4 * 4 + r][j] = x[((size_t)b * 96 + ic) * 16384 + hw0 + j];
    }
    __syncthreads();
#pragma unroll
    for (int r = 0; r < 4; r++) {
        int hwl = i4 * 4 + r;
        float v = tile[j][hwl];
        __half hi = __float2half(v);
        __half lo = __float2half(v - __half2float(hi));
        size_t idx = ((size_t)b * 16384 + hw0 + hwl) * 96 + ic0 + j;
        g_xh[idx] = hi;
        g_xl[idx] = lo;
    }
}

// ---------------------------------------------------------------------------
// Conv via mma.sync implicit GEMM + FUSED row-FFT epilogue.
// 2 k16-chunks per iteration, 2-slot x 2-chunk weight ring (27 barriers).
// Outputs y (fp16) and u (half2 complex) directly.
// ---------------------------------------------------------------------------
#define XS_ELEMS 40560              // 3*130*104 fp16 per copy
#define WSLOT_OFF_B 162240          // bytes: 2 copies * XS_ELEMS * 2B
#define PAIR_HALF 9216              // 2 chunks * 4608 fp16
#define CONV_SMEM (WSLOT_OFF_B + 2 * PAIR_HALF * 2)
#define STG_STRIDE 264

__global__ void __launch_bounds__(256) conv_mma_kernel() {
    extern __shared__ char sd[];
    __half* xsH = (__half*)sd;
    __half* xsL = xsH + XS_ELEMS;
    __half* wring = (__half*)(sd + WSLOT_OFF_B);

    int t = threadIdx.x;
    int h = blockIdx.x;
    int b = blockIdx.y;
    int wid = t >> 5, lane = t & 31;
    int g = lane >> 2, tig = lane & 3;
    int ocbase = (wid >> 2) * 96;
    int pxbase = (wid & 3) * 32;

    // Preload chunk-pair 0 (chunks 0,1): 1152 x 16B
    uint32_t wring_s = smem_u32(wring);
    for (int i = t; i < 1152; i += 256)
        cp_async16(wring_s + i * 16, (const char*)g_wimg + i * 16);
    cp_commit();

    // Stage input rows (hi & lo) with halo: [3 kh][130 ww][104 ic]
    {
        const __half* xb_h = g_xh + (size_t)b * 16384 * 96;
        const __half* xb_l = g_xl + (size_t)b * 16384 * 96;
        for (int idx = t; idx < 4680; idx += 256) {
            int c16 = idx % 12;
            int ww = (idx / 12) % 130;
            int kh = idx / (12 * 130);
            int hp = h + kh - 1;
            int wp = ww - 1;
            uint4 vh = make_uint4(0, 0, 0, 0), vl = vh;
            if (hp >= 0 && hp < 128 && wp >= 0 && wp < 128) {
                size_t src = ((size_t)hp * 128 + wp) * 96 + c16 * 8;
                vh = *(const uint4*)(xb_h + src);
                vl = *(const uint4*)(xb_l + src);
            }
            int dst = kh * 13520 + ww * 104 + c16 * 8;
            *(uint4*)(xsH + dst) = vh;
            *(uint4*)(xsL + dst) = vl;
        }
    }
    cp_wait0();
    __syncthreads();

    float acc[6][4][4];
#pragma unroll
    for (int m = 0; m < 6; m++)
#pragma unroll
        for (int n = 0; n < 4; n++)
#pragma unroll
            for (int q = 0; q < 4; q++) acc[m][n][q] = 0.0f;

    for (int it = 0; it < 27; it++) {
        if (it < 26) {
            uint32_t dsts = wring_s + ((it + 1) & 1) * (PAIR_HALF * 2);
            const char* srcg = (const char*)g_wimg + (size_t)(it + 1) * (PAIR_HALF * 2);
            for (int i = t; i < 1152; i += 256)
                cp_async16(dsts + i * 16, srcg + i * 16);
            cp_commit();
        }

#pragma unroll
        for (int sub = 0; sub < 2; sub++) {
            int c = 2 * it + sub;
            int tap = c / 6, icg = c % 6;
            int kh = tap / 3, kw = tap % 3;
            const __half* wslot = wring + ((it & 1) * 2 + sub) * 4608;

            uint32_t bh0[4], bh1[4], bl0[4], bl1[4];
            int rowb = kh * 130 + pxbase + kw + g;
            int icoff = icg * 16 + 2 * tig;
#pragma unroll
            for (int n = 0; n < 4; n++) {
                int off = (rowb + n * 8) * 104 + icoff;
                bh0[n] = *(const uint32_t*)(xsH + off);
                bh1[n] = *(const uint32_t*)(xsH + off + 8);
                bl0[n] = *(const uint32_t*)(xsL + off);
                bl1[n] = *(const uint32_t*)(xsL + off + 8);
            }
#pragma unroll
            for (int m = 0; m < 6; m++) {
                const __half* pA = wslot + (ocbase + m * 16 + g) * 24 + 2 * tig;
                uint32_t a0 = *(const uint32_t*)pA;
                uint32_t a1 = *(const uint32_t*)(pA + 192);
                uint32_t a2 = *(const uint32_t*)(pA + 8);
                uint32_t a3 = *(const uint32_t*)(pA + 200);
#pragma unroll
                for (int n = 0; n < 4; n++) {
                    mma16816(acc[m][n], a0, a1, a2, a3, bh0[n], bh1[n]);
                    mma16816(acc[m][n], a0, a1, a2, a3, bl0[n], bl1[n]);
                }
            }
        }
        if (it < 26) cp_wait0();
        __syncthreads();
    }

    // ---- Fused epilogue: stage pixel-shuffled D, then per-warp row FFT ----
    float* stage = (float*)sd;   // 96 rows x 264 f32 = 101376 B (xs region, done)
#pragma unroll
    for (int m = 0; m < 6; m++) {
#pragma unroll
        for (int n = 0; n < 4; n++) {
#pragma unroll
            for (int q = 0; q < 4; q++) {
                int oc = ocbase + m * 16 + g + 8 * (q >> 1);
                int px = pxbase + n * 8 + 2 * tig + (q & 1);
                int r2 = oc >> 1;
                int col = 2 * px + (oc & 1);
                stage[r2 * STG_STRIDE + col] = acc[m][n][q];
            }
        }
    }
    __syncthreads();

    FTw tw;
    make_tw(lane, tw);
    const float sc = 1.0f / 256.0f;
#pragma unroll 1
    for (int rr = 0; rr < 12; rr++) {
        int r2 = wid * 12 + rr;
        const float* rowp = stage + r2 * STG_STRIDE;
        float4 v0 = *(const float4*)(rowp + 8 * lane);
        float4 v1 = *(const float4*)(rowp + 8 * lane + 4);
        size_t grow = ((size_t)b * 48 + (r2 >> 1)) * 256 + 2 * h + (r2 & 1);
        // y fp16 store (coalesced 16B per lane)
        ((uint4*)(g_yh + grow * 256))[lane] =
            make_uint4(pack_h2(v0.x, v0.y), pack_h2(v0.z, v0.w),
                       pack_h2(v1.x, v1.y), pack_h2(v1.z, v1.w));
        float2 d[8];
        d[0] = make_float2(v0.x, 0.f); d[1] = make_float2(v0.y, 0.f);
        d[2] = make_float2(v0.z, 0.f); d[3] = make_float2(v0.w, 0.f);
        d[4] = make_float2(v1.x, 0.f); d[5] = make_float2(v1.y, 0.f);
        d[6] = make_float2(v1.z, 0.f); d[7] = make_float2(v1.w, 0.f);
        fft_fwd(d, tw, lane);
        apply_mask(d);
        fft_inv(d, tw, lane);
        // u half2 store (2 x 16B per lane)
        uint4* ur = (uint4*)(g_uh + grow * 256);
        ur[lane * 2] = make_uint4(pack_h2(d[0].x * sc, d[0].y * sc),
                                  pack_h2(d[1].x * sc, d[1].y * sc),
                                  pack_h2(d[2].x * sc, d[2].y * sc),
                                  pack_h2(d[3].x * sc, d[3].y * sc));
        ur[lane * 2 + 1] = make_uint4(pack_h2(d[4].x * sc, d[4].y * sc),
                                      pack_h2(d[5].x * sc, d[5].y * sc),
                                      pack_h2(d[6].x * sc, d[6].y * sc),
                                      pack_h2(d[7].x * sc, d[7].y * sc));
    }
}

// ---------------------------------------------------------------------------
// Column pass + magnitude + combine. 32 cols/block, dynamic smem 64KB+.
// ---------------------------------------------------------------------------
#define COL_SMEM (32 * 257 * 8)

__global__ void __launch_bounds__(256) col_kernel(const float* __restrict__ beta,
                                                  float* __restrict__ out) {
    extern __shared__ float2 tile[];   // [32][257]
    int t = threadIdx.x;
    int img = blockIdx.x >> 3;
    int c0 = (blockIdx.x & 7) << 5;
    size_t ibase = (size_t)img * 65536;
    const uint32_t* ub = g_uh + ibase;

    int cL = t & 31;
    int rg = t >> 5;
#pragma unroll 4
    for (int k = 0; k < 32; k++) {
        int r = rg + k * 8;
        tile[cL * 257 + ((r & 7) << 5) + (r >> 3)] = unpack_h2(ub[(size_t)r * 256 + c0 + cL]);
    }
    __syncthreads();

    int lane = t & 31;
    int wp = t >> 5;
    FTw tw;
    make_tw(lane, tw);
    const float sc = 1.0f / 256.0f;
#pragma unroll 1
    for (int cc = 0; cc < 4; cc++) {
        int cl = wp * 4 + cc;
        float2 d[8];
#pragma unroll
        for (int j = 0; j < 8; j++) d[j] = tile[cl * 257 + j * 32 + lane];
        fft_fwd(d, tw, lane);
        apply_mask(d);
        fft_inv(d, tw, lane);
#pragma unroll
        for (int j = 0; j < 8; j++) {
            float vx = d[j].x * sc, vy = d[j].y * sc;
            tile[cl * 257 + j * 32 + lane].x = sqrtf(vx * vx + vy * vy);
        }
    }
    __syncthreads();

    float be = *beta;
    float a0 = be;
    float a1 = 1.0f - 2.0f * be;
    int c2 = (t & 15) * 2;
    int rg2 = t >> 4;
#pragma unroll 4
    for (int k = 0; k < 16; k++) {
        int r = rg2 + k * 16;
        size_t gg = ibase + (size_t)r * 256 + c0 + c2;
        float2 yf = unpack_h2(*(const uint32_t*)(g_yh + gg));
        int p = ((r & 7) << 5) + (r >> 3);
        float m0 = tile[c2 * 257 + p].x;
        float m1 = tile[(c2 + 1) * 257 + p].x;
        *(float2*)(out + gg) = make_float2(a0 * yf.x + a1 * m0, a0 * yf.y + a1 * m1);
    }
}

// ---------------------------------------------------------------------------
extern "C" void kernel_launch(void* const* d_in, const int* in_sizes, int n_in,
                              void* d_out, int out_size) {
    const float* x = (const float*)d_in[0];
    const float* w = (const float*)d_in[1];
    const float* beta = (const float*)d_in[2];
    float* out = (float*)d_out;

    cudaFuncSetAttribute(conv_mma_kernel, cudaFuncAttributeMaxDynamicSharedMemorySize, CONV_SMEM);
    cudaFuncSetAttribute(col_kernel, cudaFuncAttributeMaxDynamicSharedMemorySize, COL_SMEM);

    wprep_kernel<<<972, 256>>>(w);
    xprep_kernel<<<dim3(512, 3, 8), 256>>>(x);
    conv_mma_kernel<<<dim3(128, 8), 256, CONV_SMEM>>>();
    col_kernel<<<384 * 8, 256, COL_SMEM>>>(beta, out);
}

// round 7
// speedup vs baseline: 3.5548x; 1.2388x over previous
#include <cuda_runtime.h>
#include <cuda_fp16.h>
#include <math.h>
#include <stdint.h>

#define PI_F 3.14159265358979f

// ---------------------------------------------------------------------------
// Scratch (__device__ globals; no runtime alloc)
// ---------------------------------------------------------------------------
__device__ __half    g_yh[25165824];      // conv output fp16, pixel-shuffled (8,48,256,256)
__device__ uint32_t  g_uh[25165824];      // row-filtered complex field, half2 (re,im) per pixel
__device__ __half    g_xh[12582912];      // x transposed [b][hw][ic], fp16
__device__ __half    g_wimg[248832];      // weights fp16: 54 chunks x [192 oc][24 k]

// ---------------------------------------------------------------------------
// mma.sync (fp16 in, f32 acc)
// ---------------------------------------------------------------------------
__device__ __forceinline__ void mma16816(float c[4],
                                         uint32_t a0, uint32_t a1, uint32_t a2, uint32_t a3,
                                         uint32_t b0, uint32_t b1) {
    asm volatile(
        "mma.sync.aligned.m16n8k16.row.col.f32.f16.f16.f32 "
        "{%0,%1,%2,%3}, {%4,%5,%6,%7}, {%8,%9}, {%0,%1,%2,%3};"
        : "+f"(c[0]), "+f"(c[1]), "+f"(c[2]), "+f"(c[3])
        : "r"(a0), "r"(a1), "r"(a2), "r"(a3), "r"(b0), "r"(b1));
}

__device__ __forceinline__ uint32_t smem_u32(const void* p) {
    uint32_t a;
    asm("{ .reg .u64 t; cvta.to.shared.u64 t, %1; cvt.u32.u64 %0, t; }" : "=r"(a) : "l"(p));
    return a;
}
__device__ __forceinline__ void cp_async16(uint32_t dst, const void* src) {
    asm volatile("cp.async.cg.shared.global [%0], [%1], 16;" :: "r"(dst), "l"(src));
}
__device__ __forceinline__ void cp_commit() { asm volatile("cp.async.commit_group;"); }
__device__ __forceinline__ void cp_wait0()  { asm volatile("cp.async.wait_group 0;"); }

// pack two floats -> half2 (lo = a, hi = b)
__device__ __forceinline__ uint32_t pack_h2(float a, float b) {
    uint32_t r;
    asm("cvt.rn.f16x2.f32 %0, %1, %2;" : "=r"(r) : "f"(b), "f"(a));
    return r;
}
__device__ __forceinline__ float2 unpack_h2(uint32_t v) {
    __half2 h = *reinterpret_cast<const __half2*>(&v);
    return __half22float2(h);
}

// ---------------------------------------------------------------------------
// Warp-FFT machinery (fast __sincosf twiddles)
// ---------------------------------------------------------------------------
__device__ __forceinline__ float2 cadd(float2 a, float2 b) { return make_float2(a.x + b.x, a.y + b.y); }
__device__ __forceinline__ float2 csub(float2 a, float2 b) { return make_float2(a.x - b.x, a.y - b.y); }
__device__ __forceinline__ float2 cmul(float2 a, float2 b) {
    return make_float2(a.x * b.x - a.y * b.y, a.x * b.y + a.y * b.x);
}
__device__ __forceinline__ float2 expi(float a) {
    float s, c;
    __sincosf(a, &s, &c);
    return make_float2(c, s);
}
__device__ __forceinline__ float2 shflxc(float2 v, int m) {
    v.x = __shfl_xor_sync(0xffffffffu, v.x, m);
    v.y = __shfl_xor_sync(0xffffffffu, v.y, m);
    return v;
}

struct FTw { float2 ws[5]; float2 m[8]; };

__device__ __forceinline__ void make_tw(int lane, FTw& t) {
    int brl = __brev((unsigned)lane) >> 27;
    t.ws[0] = expi(-PI_F * (float)(lane & 15) / 16.0f);
    t.ws[1] = expi(-PI_F * (float)(lane & 7) / 8.0f);
    t.ws[2] = expi(-PI_F * (float)(lane & 3) / 4.0f);
    t.ws[3] = expi(-PI_F * (float)(lane & 1) / 2.0f);
    t.ws[4] = make_float2(1.0f, 0.0f);
    float2 mb = expi(-2.0f * PI_F * (float)brl / 256.0f);
    t.m[0] = make_float2(1.0f, 0.0f);
#pragma unroll
    for (int j = 1; j < 8; j++) t.m[j] = cmul(t.m[j - 1], mb);
}

__device__ __forceinline__ void fft_fwd(float2 d[8], const FTw& t, int lane) {
#pragma unroll
    for (int s = 0; s < 5; s++) {
        int S = 16 >> s;
        float2 w = t.ws[s];
        bool hi = (lane & S) != 0;
#pragma unroll
        for (int j = 0; j < 8; j++) {
            float2 o = shflxc(d[j], S);
            d[j] = hi ? cmul(csub(o, d[j]), w) : cadd(d[j], o);
        }
    }
#pragma unroll
    for (int j = 1; j < 8; j++) d[j] = cmul(d[j], t.m[j]);
    const float R = 0.70710678118654752f;
    const float2 W81 = make_float2(R, -R);
    const float2 W83 = make_float2(-R, -R);
    {
        float2 u, v, tt;
        u = d[0]; v = d[4]; d[0] = cadd(u, v); d[4] = csub(u, v);
        u = d[1]; v = d[5]; d[1] = cadd(u, v); d[5] = cmul(csub(u, v), W81);
        u = d[2]; v = d[6]; d[2] = cadd(u, v); tt = csub(u, v); d[6] = make_float2(tt.y, -tt.x);
        u = d[3]; v = d[7]; d[3] = cadd(u, v); d[7] = cmul(csub(u, v), W83);
    }
#pragma unroll
    for (int gg = 0; gg < 8; gg += 4) {
        float2 u, v, tt;
        u = d[gg];     v = d[gg + 2]; d[gg] = cadd(u, v);     d[gg + 2] = csub(u, v);
        u = d[gg + 1]; v = d[gg + 3]; tt = csub(u, v);
        d[gg + 1] = cadd(u, v); d[gg + 3] = make_float2(tt.y, -tt.x);
    }
#pragma unroll
    for (int gg = 0; gg < 8; gg += 2) {
        float2 u = d[gg], v = d[gg + 1];
        d[gg] = cadd(u, v); d[gg + 1] = csub(u, v);
    }
}

__device__ __forceinline__ void fft_inv(float2 d[8], const FTw& t, int lane) {
    const float R = 0.70710678118654752f;
    const float2 W81c = make_float2(R, R);
    const float2 W83c = make_float2(-R, R);
#pragma unroll
    for (int gg = 0; gg < 8; gg += 2) {
        float2 a = d[gg], b = d[gg + 1];
        d[gg] = cadd(a, b); d[gg + 1] = csub(a, b);
    }
#pragma unroll
    for (int gg = 0; gg < 8; gg += 4) {
        float2 a, b, vb;
        a = d[gg];     b = d[gg + 2]; d[gg] = cadd(a, b); d[gg + 2] = csub(a, b);
        a = d[gg + 1]; b = d[gg + 3]; vb = make_float2(-b.y, b.x);
        d[gg + 1] = cadd(a, vb); d[gg + 3] = csub(a, vb);
    }
    {
        float2 a, v;
        a = d[0]; v = d[4];                d[0] = cadd(a, v); d[4] = csub(a, v);
        a = d[1]; v = cmul(d[5], W81c);    d[1] = cadd(a, v); d[5] = csub(a, v);
        a = d[2]; { float2 bq = d[6]; v = make_float2(-bq.y, bq.x); } d[2] = cadd(a, v); d[6] = csub(a, v);
        a = d[3]; v = cmul(d[7], W83c);    d[3] = cadd(a, v); d[7] = csub(a, v);
    }
#pragma unroll
    for (int j = 1; j < 8; j++) {
        float2 mc = make_float2(t.m[j].x, -t.m[j].y);
        d[j] = cmul(d[j], mc);
    }
#pragma unroll
    for (int s = 0; s < 5; s++) {
        int S = 1 << s;
        float2 w = t.ws[4 - s];
        float2 wc = make_float2(w.x, -w.y);
        bool hi = (lane & S) != 0;
#pragma unroll
        for (int j = 0; j < 8; j++) {
            float2 pre = hi ? cmul(d[j], wc) : d[j];
            float2 o = shflxc(pre, S);
            d[j] = hi ? csub(o, pre) : cadd(pre, o);
        }
    }
}

__device__ __forceinline__ void apply_mask(float2 d[8]) {
    d[1] = make_float2(0.f, 0.f);
    d[2] = make_float2(0.f, 0.f);
    d[5] = make_float2(0.f, 0.f);
    d[6] = make_float2(0.f, 0.f);
}

// ---------------------------------------------------------------------------
// Prep 1: weights -> fp16 image per k16 chunk: wimg[c*4608 + oc*24 + j]
// ---------------------------------------------------------------------------
__global__ void wprep_kernel(const float* __restrict__ wgt) {
    int i = blockIdx.x * 256 + threadIdx.x;
    if (i >= 248832) return;
    int j = i % 24;
    int oc = (i / 24) % 192;
    int c = i / (24 * 192);
    int tap = c / 6, icg = c % 6;
    int kh = tap / 3, kw = tap % 3;
    float w = 0.0f;
    if (j < 16) {
        int ic = icg * 16 + j;
        w = wgt[((size_t)oc * 96 + ic) * 9 + kh * 3 + kw];
    }
    g_wimg[c * 4608 + oc * 24 + j] = __float2half(w);
}

// ---------------------------------------------------------------------------
// Prep 2: transpose x (b,ic,h,w) f32 -> (b, hw, ic) fp16
// ---------------------------------------------------------------------------
__global__ void __launch_bounds__(256) xprep_kernel(const float* __restrict__ x) {
    __shared__ float tile[32][33];
    int t = threadIdx.x;
    int j = t & 31, i4 = t >> 5;
    int hw0 = blockIdx.x * 32;
    int ic0 = blockIdx.y * 32;
    int b = blockIdx.z;
#pragma unroll
    for (int r = 0; r < 4; r++) {
        int ic = ic0 + i4 * 4 + r;
        tile[i4 * 4 + r][j] = x[((size_t)b * 96 + ic) * 16384 + hw0 + j];
    }
    __syncthreads();
#pragma unroll
    for (int r = 0; r < 4; r++) {
        int hwl = i4 * 4 + r;
        float v = tile[j][hwl];
        size_t idx = ((size_t)b * 16384 + hw0 + hwl) * 96 + ic0 + j;
        g_xh[idx] = __float2half(v);
    }
}

// ---------------------------------------------------------------------------
// Conv via mma.sync implicit GEMM (single fp16 product) + fused row-FFT.
// ---------------------------------------------------------------------------
#define XS_ELEMS 40560              // 3*130*104 fp16
#define WSLOT_OFF_B 81120           // bytes: XS_ELEMS * 2B
#define PAIR_HALF 9216              // 2 chunks * 4608 fp16
#define CONV_SMEM (WSLOT_OFF_B + 2 * PAIR_HALF * 2)
#define STG_STRIDE 264

__global__ void __launch_bounds__(256) conv_mma_kernel() {
    extern __shared__ char sd[];
    __half* xsH = (__half*)sd;
    __half* wring = (__half*)(sd + WSLOT_OFF_B);

    int t = threadIdx.x;
    int h = blockIdx.x;
    int b = blockIdx.y;
    int wid = t >> 5, lane = t & 31;
    int g = lane >> 2, tig = lane & 3;
    int ocbase = (wid >> 2) * 96;
    int pxbase = (wid & 3) * 32;

    // Preload chunk-pair 0 (chunks 0,1): 1152 x 16B
    uint32_t wring_s = smem_u32(wring);
    for (int i = t; i < 1152; i += 256)
        cp_async16(wring_s + i * 16, (const char*)g_wimg + i * 16);
    cp_commit();

    // Stage input rows with halo: [3 kh][130 ww][104 ic]
    {
        const __half* xb_h = g_xh + (size_t)b * 16384 * 96;
        for (int idx = t; idx < 4680; idx += 256) {
            int c16 = idx % 12;
            int ww = (idx / 12) % 130;
            int kh = idx / (12 * 130);
            int hp = h + kh - 1;
            int wp = ww - 1;
            uint4 vh = make_uint4(0, 0, 0, 0);
            if (hp >= 0 && hp < 128 && wp >= 0 && wp < 128) {
                size_t src = ((size_t)hp * 128 + wp) * 96 + c16 * 8;
                vh = *(const uint4*)(xb_h + src);
            }
            int dst = kh * 13520 + ww * 104 + c16 * 8;
            *(uint4*)(xsH + dst) = vh;
        }
    }
    cp_wait0();
    __syncthreads();

    float acc[6][4][4];
#pragma unroll
    for (int m = 0; m < 6; m++)
#pragma unroll
        for (int n = 0; n < 4; n++)
#pragma unroll
            for (int q = 0; q < 4; q++) acc[m][n][q] = 0.0f;

    for (int it = 0; it < 27; it++) {
        if (it < 26) {
            uint32_t dsts = wring_s + ((it + 1) & 1) * (PAIR_HALF * 2);
            const char* srcg = (const char*)g_wimg + (size_t)(it + 1) * (PAIR_HALF * 2);
            for (int i = t; i < 1152; i += 256)
                cp_async16(dsts + i * 16, srcg + i * 16);
            cp_commit();
        }

#pragma unroll
        for (int sub = 0; sub < 2; sub++) {
            int c = 2 * it + sub;
            int tap = c / 6, icg = c % 6;
            int kh = tap / 3, kw = tap % 3;
            const __half* wslot = wring + ((it & 1) * 2 + sub) * 4608;

            uint32_t bh0[4], bh1[4];
            int rowb = kh * 130 + pxbase + kw + g;
            int icoff = icg * 16 + 2 * tig;
#pragma unroll
            for (int n = 0; n < 4; n++) {
                int off = (rowb + n * 8) * 104 + icoff;
                bh0[n] = *(const uint32_t*)(xsH + off);
                bh1[n] = *(const uint32_t*)(xsH + off + 8);
            }
#pragma unroll
            for (int m = 0; m < 6; m++) {
                const __half* pA = wslot + (ocbase + m * 16 + g) * 24 + 2 * tig;
                uint32_t a0 = *(const uint32_t*)pA;
                uint32_t a1 = *(const uint32_t*)(pA + 192);
                uint32_t a2 = *(const uint32_t*)(pA + 8);
                uint32_t a3 = *(const uint32_t*)(pA + 200);
#pragma unroll
                for (int n = 0; n < 4; n++) {
                    mma16816(acc[m][n], a0, a1, a2, a3, bh0[n], bh1[n]);
                }
            }
        }
        if (it < 26) cp_wait0();
        __syncthreads();
    }

    // ---- Fused epilogue: stage pixel-shuffled D, then per-warp row FFT ----
    float* stage = (float*)sd;   // 96 rows x 264 f32 = 101376 B
#pragma unroll
    for (int m = 0; m < 6; m++) {
#pragma unroll
        for (int n = 0; n < 4; n++) {
#pragma unroll
            for (int q = 0; q < 4; q++) {
                int oc = ocbase + m * 16 + g + 8 * (q >> 1);
                int px = pxbase + n * 8 + 2 * tig + (q & 1);
                int r2 = oc >> 1;
                int col = 2 * px + (oc & 1);
                stage[r2 * STG_STRIDE + col] = acc[m][n][q];
            }
        }
    }
    __syncthreads();

    FTw tw;
    make_tw(lane, tw);
    const float sc = 1.0f / 256.0f;
#pragma unroll 1
    for (int rr = 0; rr < 12; rr++) {
        int r2 = wid * 12 + rr;
        const float* rowp = stage + r2 * STG_STRIDE;
        float4 v0 = *(const float4*)(rowp + 8 * lane);
        float4 v1 = *(const float4*)(rowp + 8 * lane + 4);
        size_t grow = ((size_t)b * 48 + (r2 >> 1)) * 256 + 2 * h + (r2 & 1);
        ((uint4*)(g_yh + grow * 256))[lane] =
            make_uint4(pack_h2(v0.x, v0.y), pack_h2(v0.z, v0.w),
                       pack_h2(v1.x, v1.y), pack_h2(v1.z, v1.w));
        float2 d[8];
        d[0] = make_float2(v0.x, 0.f); d[1] = make_float2(v0.y, 0.f);
        d[2] = make_float2(v0.z, 0.f); d[3] = make_float2(v0.w, 0.f);
        d[4] = make_float2(v1.x, 0.f); d[5] = make_float2(v1.y, 0.f);
        d[6] = make_float2(v1.z, 0.f); d[7] = make_float2(v1.w, 0.f);
        fft_fwd(d, tw, lane);
        apply_mask(d);
        fft_inv(d, tw, lane);
        uint4* ur = (uint4*)(g_uh + grow * 256);
        ur[lane * 2] = make_uint4(pack_h2(d[0].x * sc, d[0].y * sc),
                                  pack_h2(d[1].x * sc, d[1].y * sc),
                                  pack_h2(d[2].x * sc, d[2].y * sc),
                                  pack_h2(d[3].x * sc, d[3].y * sc));
        ur[lane * 2 + 1] = make_uint4(pack_h2(d[4].x * sc, d[4].y * sc),
                                      pack_h2(d[5].x * sc, d[5].y * sc),
                                      pack_h2(d[6].x * sc, d[6].y * sc),
                                      pack_h2(d[7].x * sc, d[7].y * sc));
    }
}

// ---------------------------------------------------------------------------
// Column pass + magnitude + combine. Tile kept as packed half2 (uint32)
// -> 32.9KB smem per CTA for occupancy.
// ---------------------------------------------------------------------------
#define COL_SMEM (32 * 257 * 4)

__global__ void __launch_bounds__(256) col_kernel(const float* __restrict__ beta,
                                                  float* __restrict__ out) {
    extern __shared__ uint32_t tileu[];   // [32][257] packed half2 / f32 mag
    int t = threadIdx.x;
    int img = blockIdx.x >> 3;
    int c0 = (blockIdx.x & 7) << 5;
    size_t ibase = (size_t)img * 65536;
    const uint32_t* ub = g_uh + ibase;

    int cL = t & 31;
    int rg = t >> 5;
#pragma unroll 4
    for (int k = 0; k < 32; k++) {
        int r = rg + k * 8;
        tileu[cL * 257 + ((r & 7) << 5) + (r >> 3)] = ub[(size_t)r * 256 + c0 + cL];
    }
    __syncthreads();

    int lane = t & 31;
    int wp = t >> 5;
    FTw tw;
    make_tw(lane, tw);
    const float sc = 1.0f / 256.0f;
#pragma unroll 1
    for (int cc = 0; cc < 4; cc++) {
        int cl = wp * 4 + cc;
        float2 d[8];
#pragma unroll
        for (int j = 0; j < 8; j++) d[j] = unpack_h2(tileu[cl * 257 + j * 32 + lane]);
        fft_fwd(d, tw, lane);
        apply_mask(d);
        fft_inv(d, tw, lane);
#pragma unroll
        for (int j = 0; j < 8; j++) {
            float vx = d[j].x * sc, vy = d[j].y * sc;
            tileu[cl * 257 + j * 32 + lane] = __float_as_uint(sqrtf(vx * vx + vy * vy));
        }
    }
    __syncthreads();

    float be = *beta;
    float a0 = be;
    float a1 = 1.0f - 2.0f * be;
    int c2 = (t & 15) * 2;
    int rg2 = t >> 4;
#pragma unroll 4
    for (int k = 0; k < 16; k++) {
        int r = rg2 + k * 16;
        size_t gg = ibase + (size_t)r * 256 + c0 + c2;
        float2 yf = unpack_h2(*(const uint32_t*)(g_yh + gg));
        int p = ((r & 7) << 5) + (r >> 3);
        float m0 = __uint_as_float(tileu[c2 * 257 + p]);
        float m1 = __uint_as_float(tileu[(c2 + 1) * 257 + p]);
        *(float2*)(out + gg) = make_float2(a0 * yf.x + a1 * m0, a0 * yf.y + a1 * m1);
    }
}

// ---------------------------------------------------------------------------
extern "C" void kernel_launch(void* const* d_in, const int* in_sizes, int n_in,
                              void* d_out, int out_size) {
    const float* x = (const float*)d_in[0];
    const float* w = (const float*)d_in[1];
    const float* beta = (const float*)d_in[2];
    float* out = (float*)d_out;

    cudaFuncSetAttribute(conv_mma_kernel, cudaFuncAttributeMaxDynamicSharedMemorySize, CONV_SMEM);
    cudaFuncSetAttribute(col_kernel, cudaFuncAttributeMaxDynamicSharedMemorySize, COL_SMEM);

    wprep_kernel<<<972, 256>>>(w);
    xprep_kernel<<<dim3(512, 3, 8), 256>>>(x);
    conv_mma_kernel<<<dim3(128, 8), 256, CONV_SMEM>>>();
    col_kernel<<<384 * 8, 256, COL_SMEM>>>(beta, out);
}

// round 9
// speedup vs baseline: 4.1617x; 1.1707x over previous
#include <cuda_runtime.h>
#include <cuda_fp16.h>
#include <math.h>
#include <stdint.h>

#define PI_F 3.14159265358979f

// ---------------------------------------------------------------------------
// Scratch (__device__ globals; no runtime alloc)
// ---------------------------------------------------------------------------
__device__ __half    g_yh[25165824];      // conv output fp16, pixel-shuffled (8,48,256,256)
__device__ uint32_t  g_uh[25165824];      // row-filtered complex field, half2 (re,im)
__device__ __half    g_xh[12582912];      // x transposed [b][hw][ic], fp16
__device__ __half    g_wimg[248832];      // weights fp16: 54 chunks x [192 oc][24 k]

// ---------------------------------------------------------------------------
// mma.sync (fp16 in, f32 acc)
// ---------------------------------------------------------------------------
__device__ __forceinline__ void mma16816(float c[4],
                                         uint32_t a0, uint32_t a1, uint32_t a2, uint32_t a3,
                                         uint32_t b0, uint32_t b1) {
    asm volatile(
        "mma.sync.aligned.m16n8k16.row.col.f32.f16.f16.f32 "
        "{%0,%1,%2,%3}, {%4,%5,%6,%7}, {%8,%9}, {%0,%1,%2,%3};"
        : "+f"(c[0]), "+f"(c[1]), "+f"(c[2]), "+f"(c[3])
        : "r"(a0), "r"(a1), "r"(a2), "r"(a3), "r"(b0), "r"(b1));
}

__device__ __forceinline__ uint32_t smem_u32(const void* p) {
    uint32_t a;
    asm("{ .reg .u64 t; cvta.to.shared.u64 t, %1; cvt.u32.u64 %0, t; }" : "=r"(a) : "l"(p));
    return a;
}
__device__ __forceinline__ void cp_async16(uint32_t dst, const void* src) {
    asm volatile("cp.async.cg.shared.global [%0], [%1], 16;" :: "r"(dst), "l"(src));
}
__device__ __forceinline__ void cp_async16z(uint32_t dst, const void* src, bool inb) {
    int sz = inb ? 16 : 0;
    asm volatile("cp.async.cg.shared.global [%0], [%1], 16, %2;" :: "r"(dst), "l"(src), "r"(sz));
}
__device__ __forceinline__ void cp_commit() { asm volatile("cp.async.commit_group;"); }
__device__ __forceinline__ void cp_wait0()  { asm volatile("cp.async.wait_group 0;"); }

__device__ __forceinline__ uint32_t pack_h2(float a, float b) {
    uint32_t r;
    asm("cvt.rn.f16x2.f32 %0, %1, %2;" : "=r"(r) : "f"(b), "f"(a));
    return r;
}
__device__ __forceinline__ float2 unpack_h2(uint32_t v) {
    __half2 h = *reinterpret_cast<const __half2*>(&v);
    return __half22float2(h);
}

// ---------------------------------------------------------------------------
// Fused H = IFFT * mask * FFT (256-pt, one warp), lean twiddle state.
// ---------------------------------------------------------------------------
__device__ __forceinline__ float2 cadd(float2 a, float2 b) { return make_float2(a.x + b.x, a.y + b.y); }
__device__ __forceinline__ float2 csub(float2 a, float2 b) { return make_float2(a.x - b.x, a.y - b.y); }
__device__ __forceinline__ float2 cmul(float2 a, float2 b) {
    return make_float2(a.x * b.x - a.y * b.y, a.x * b.y + a.y * b.x);
}
__device__ __forceinline__ float2 cconj(float2 a) { return make_float2(a.x, -a.y); }
__device__ __forceinline__ float2 expi(float a) {
    float s, c;
    __sincosf(a, &s, &c);
    return make_float2(c, s);
}
__device__ __forceinline__ float2 shflxc(float2 v, int m) {
    v.x = __shfl_xor_sync(0xffffffffu, v.x, m);
    v.y = __shfl_xor_sync(0xffffffffu, v.y, m);
    return v;
}

struct FTw2 { float2 ws0, ws1, ws2, ws3, mb; };

__device__ __forceinline__ void make_tw2(int lane, FTw2& t) {
    int brl = __brev((unsigned)lane) >> 27;
    t.ws0 = expi(-PI_F * (float)(lane & 15) / 16.0f);
    t.ws1 = expi(-PI_F * (float)(lane & 7) / 8.0f);
    const float R = 0.70710678118654752f;
    int a2 = lane & 3;
    t.ws2 = (a2 == 0) ? make_float2(1.f, 0.f)
          : (a2 == 1) ? make_float2(R, -R)
          : (a2 == 2) ? make_float2(0.f, -1.f)
                      : make_float2(-R, -R);
    t.ws3 = (lane & 1) ? make_float2(0.f, -1.f) : make_float2(1.f, 0.f);
    t.mb  = expi(-2.0f * PI_F * (float)brl / 256.0f);
}

__device__ __forceinline__ void xstage_fwd(float2 d[8], int S, float2 w, int lane) {
    bool hi = (lane & S) != 0;
#pragma unroll
    for (int j = 0; j < 8; j++) {
        float2 o = shflxc(d[j], S);
        d[j] = hi ? cmul(csub(o, d[j]), w) : cadd(d[j], o);
    }
}
__device__ __forceinline__ void xstage_unity(float2 d[8], int lane) {
    bool hi = (lane & 1) != 0;
#pragma unroll
    for (int j = 0; j < 8; j++) {
        float2 o = shflxc(d[j], 1);
        d[j] = hi ? csub(o, d[j]) : cadd(d[j], o);
    }
}
__device__ __forceinline__ void xstage_inv(float2 d[8], int S, float2 wc, int lane) {
    bool hi = (lane & S) != 0;
#pragma unroll
    for (int j = 0; j < 8; j++) {
        float2 pre = hi ? cmul(d[j], wc) : d[j];
        float2 o = shflxc(pre, S);
        d[j] = hi ? csub(o, pre) : cadd(pre, o);
    }
}

// Full fused operator. Input: natural-order samples (lane l, reg j = x[8l+j]).
// Output: H(x) in the same layout, unscaled (caller multiplies by 1/256).
__device__ __forceinline__ void apply_H(float2 d[8], const FTw2& t, int lane) {
    xstage_fwd(d, 16, t.ws0, lane);
    xstage_fwd(d, 8,  t.ws1, lane);
    xstage_fwd(d, 4,  t.ws2, lane);
    xstage_fwd(d, 2,  t.ws3, lane);
    xstage_unity(d, lane);
    {
        float2 m = t.mb;
        d[1] = cmul(d[1], m);
#pragma unroll
        for (int j = 2; j < 8; j++) { m = cmul(m, t.mb); d[j] = cmul(d[j], m); }
    }
    const float R = 0.70710678118654752f;
    const float2 W81 = make_float2(R, -R);
    const float2 W83 = make_float2(-R, -R);
    {
        float2 u, v, tt;
        u = d[0]; v = d[4]; d[0] = cadd(u, v); d[4] = csub(u, v);
        u = d[1]; v = d[5]; d[1] = cadd(u, v); d[5] = cmul(csub(u, v), W81);
        u = d[2]; v = d[6]; d[2] = cadd(u, v); tt = csub(u, v); d[6] = make_float2(tt.y, -tt.x);
        u = d[3]; v = d[7]; d[3] = cadd(u, v); d[7] = cmul(csub(u, v), W83);
    }
#pragma unroll
    for (int gg = 0; gg < 8; gg += 4) {
        float2 u, v, tt;
        u = d[gg];     v = d[gg + 2]; d[gg] = cadd(u, v);     d[gg + 2] = csub(u, v);
        u = d[gg + 1]; v = d[gg + 3]; tt = csub(u, v);
        d[gg + 1] = cadd(u, v); d[gg + 3] = make_float2(tt.y, -tt.x);
    }
    // forward S1 pruned to kept bins {0,3,4,7} + mask + inverse S1+S2 folded
    {
        float2 p = cadd(d[0], d[1]);
        float2 q = csub(d[2], d[3]);
        float2 r = cadd(d[4], d[5]);
        float2 s = csub(d[6], d[7]);
        d[0] = cadd(p, q);
        d[2] = csub(p, q);
        d[1] = make_float2(p.x + q.y, p.y - q.x);   // p - i q
        d[3] = make_float2(p.x - q.y, p.y + q.x);   // p + i q
        d[4] = cadd(r, s);
        d[6] = csub(r, s);
        d[5] = make_float2(r.x + s.y, r.y - s.x);
        d[7] = make_float2(r.x - s.y, r.y + s.x);
    }
    const float2 W81c = make_float2(R, R);
    const float2 W83c = make_float2(-R, R);
    {
        float2 a, v;
        a = d[0]; v = d[4];                d[0] = cadd(a, v); d[4] = csub(a, v);
        a = d[1]; v = cmul(d[5], W81c);    d[1] = cadd(a, v); d[5] = csub(a, v);
        a = d[2]; { float2 bq = d[6]; v = make_float2(-bq.y, bq.x); } d[2] = cadd(a, v); d[6] = csub(a, v);
        a = d[3]; v = cmul(d[7], W83c);    d[3] = cadd(a, v); d[7] = csub(a, v);
    }
    {
        float2 mc = cconj(t.mb);
        float2 m = mc;
        d[1] = cmul(d[1], m);
#pragma unroll
        for (int j = 2; j < 8; j++) { m = cmul(m, mc); d[j] = cmul(d[j], m); }
    }
    xstage_unity(d, lane);
    xstage_inv(d, 2,  cconj(t.ws3), lane);
    xstage_inv(d, 4,  cconj(t.ws2), lane);
    xstage_inv(d, 8,  cconj(t.ws1), lane);
    xstage_inv(d, 16, cconj(t.ws0), lane);
}

// ---------------------------------------------------------------------------
// Prep 1: weights -> fp16 image per k16 chunk: wimg[c*4608 + oc*24 + j]
// ---------------------------------------------------------------------------
__global__ void wprep_kernel(const float* __restrict__ wgt) {
    int i = blockIdx.x * 256 + threadIdx.x;
    if (i >= 248832) return;
    int j = i % 24;
    int oc = (i / 24) % 192;
    int c = i / (24 * 192);
    int tap = c / 6, icg = c % 6;
    int kh = tap / 3, kw = tap % 3;
    float w = 0.0f;
    if (j < 16) {
        int ic = icg * 16 + j;
        w = wgt[((size_t)oc * 96 + ic) * 9 + kh * 3 + kw];
    }
    g_wimg[c * 4608 + oc * 24 + j] = __float2half(w);
}

// ---------------------------------------------------------------------------
// Prep 2: transpose x (b,ic,h,w) f32 -> (b, hw, ic) fp16
// ---------------------------------------------------------------------------
__global__ void __launch_bounds__(256) xprep_kernel(const float* __restrict__ x) {
    __shared__ float tile[32][33];
    int t = threadIdx.x;
    int j = t & 31, i4 = t >> 5;
    int hw0 = blockIdx.x * 32;
    int ic0 = blockIdx.y * 32;
    int b = blockIdx.z;
#pragma unroll
    for (int r = 0; r < 4; r++) {
        int ic = ic0 + i4 * 4 + r;
        tile[i4 * 4 + r][j] = x[((size_t)b * 96 + ic) * 16384 + hw0 + j];
    }
    __syncthreads();
#pragma unroll
    for (int r = 0; r < 4; r++) {
        int hwl = i4 * 4 + r;
        float v = tile[j][hwl];
        size_t idx = ((size_t)b * 16384 + hw0 + hwl) * 96 + ic0 + j;
        g_xh[idx] = __float2half(v);
    }
}

// ---------------------------------------------------------------------------
// Conv implicit GEMM (mma.sync fp16) + fused row-H epilogue.
// smem 101.4KB -> 2 CTAs/SM. Single-chunk weight ring (2 slots), 54 iters.
// ---------------------------------------------------------------------------
#define XS_ELEMS 40560              // 3*130*104 fp16
#define WOFF_B 81120                // bytes: XS_ELEMS * 2
#define SLOT_B 9216                 // 4608 fp16 per chunk
#define STG_STRIDE 264              // 264*4 = 1056 B, 16B-aligned rows
#define CONV_SMEM (96 * STG_STRIDE * 4)   // 101376 >= WOFF_B + 2*SLOT_B = 99552

__global__ void __launch_bounds__(256, 2) conv_mma_kernel() {
    extern __shared__ char sd[];
    __half* xsH = (__half*)sd;
    __half* wring = (__half*)(sd + WOFF_B);

    int t = threadIdx.x;
    int h = blockIdx.x;
    int b = blockIdx.y;
    int wid = t >> 5, lane = t & 31;
    int g = lane >> 2, tig = lane & 3;
    int ocbase = (wid >> 2) * 96;
    int pxbase = (wid & 3) * 32;

    // Preload chunk 0 weights (576 x 16B)
    uint32_t wring_s = smem_u32(wring);
    for (int i = t; i < 576; i += 256)
        cp_async16(wring_s + i * 16, (const char*)g_wimg + i * 16);
    cp_commit();

    // Stage input rows with halo via zfill cp.async: [3 kh][130 ww][104 ic]
    {
        const __half* xb_h = g_xh + (size_t)b * 16384 * 96;
        uint32_t xs_s = smem_u32(xsH);
        for (int idx = t; idx < 4680; idx += 256) {
            int c16 = idx % 12;
            int ww = (idx / 12) % 130;
            int kh = idx / (12 * 130);
            int hp = h + kh - 1;
            int wp = ww - 1;
            bool inb = (hp >= 0 && hp < 128 && wp >= 0 && wp < 128);
            size_t src = inb ? (((size_t)hp * 128 + wp) * 96 + c16 * 8) : 0;
            int dst = kh * 13520 + ww * 104 + c16 * 8;
            cp_async16z(xs_s + dst * 2, xb_h + src, inb);
        }
    }
    cp_commit();
    cp_wait0();
    __syncthreads();

    float acc[6][4][4];
#pragma unroll
    for (int m = 0; m < 6; m++)
#pragma unroll
        for (int n = 0; n < 4; n++)
#pragma unroll
            for (int q = 0; q < 4; q++) acc[m][n][q] = 0.0f;

    for (int c = 0; c < 54; c++) {
        if (c < 53) {
            uint32_t dsts = wring_s + ((c + 1) & 1) * SLOT_B;
            const char* srcg = (const char*)g_wimg + (size_t)(c + 1) * SLOT_B;
            for (int i = t; i < 576; i += 256)
                cp_async16(dsts + i * 16, srcg + i * 16);
            cp_commit();
        }

        int tap = c / 6, icg = c % 6;
        int kh = tap / 3, kw = tap % 3;
        const __half* wslot = wring + (c & 1) * 4608;

        uint32_t bh0[4], bh1[4];
        int rowb = kh * 130 + pxbase + kw + g;
        int icoff = icg * 16 + 2 * tig;
#pragma unroll
        for (int n = 0; n < 4; n++) {
            int off = (rowb + n * 8) * 104 + icoff;
            bh0[n] = *(const uint32_t*)(xsH + off);
            bh1[n] = *(const uint32_t*)(xsH + off + 8);
        }
#pragma unroll
        for (int m = 0; m < 6; m++) {
            const __half* pA = wslot + (ocbase + m * 16 + g) * 24 + 2 * tig;
            uint32_t a0 = *(const uint32_t*)pA;
            uint32_t a1 = *(const uint32_t*)(pA + 192);
            uint32_t a2 = *(const uint32_t*)(pA + 8);
            uint32_t a3 = *(const uint32_t*)(pA + 200);
#pragma unroll
            for (int n = 0; n < 4; n++)
                mma16816(acc[m][n], a0, a1, a2, a3, bh0[n], bh1[n]);
        }
        if (c < 53) cp_wait0();
        __syncthreads();
    }

    // ---- Fused epilogue: stage pixel-shuffled D, then per-warp row H ----
    float* stage = (float*)sd;   // 96 rows x 264 f32 = 101376 B
#pragma unroll
    for (int m = 0; m < 6; m++) {
#pragma unroll
        for (int n = 0; n < 4; n++) {
#pragma unroll
            for (int q = 0; q < 4; q++) {
                int oc = ocbase + m * 16 + g + 8 * (q >> 1);
                int px = pxbase + n * 8 + 2 * tig + (q & 1);
                int r2 = oc >> 1;
                int col = 2 * px + (oc & 1);
                stage[r2 * STG_STRIDE + col] = acc[m][n][q];
            }
        }
    }
    __syncthreads();

    FTw2 tw;
    make_tw2(lane, tw);
    const float sc = 1.0f / 256.0f;
#pragma unroll 1
    for (int rr = 0; rr < 12; rr++) {
        int r2 = wid * 12 + rr;
        const float* rowp = stage + r2 * STG_STRIDE;
        float4 v0 = *(const float4*)(rowp + 8 * lane);
        float4 v1 = *(const float4*)(rowp + 8 * lane + 4);
        size_t grow = ((size_t)b * 48 + (r2 >> 1)) * 256 + 2 * h + (r2 & 1);
        ((uint4*)(g_yh + grow * 256))[lane] =
            make_uint4(pack_h2(v0.x, v0.y), pack_h2(v0.z, v0.w),
                       pack_h2(v1.x, v1.y), pack_h2(v1.z, v1.w));
        float2 d[8];
        d[0] = make_float2(v0.x, 0.f); d[1] = make_float2(v0.y, 0.f);
        d[2] = make_float2(v0.z, 0.f); d[3] = make_float2(v0.w, 0.f);
        d[4] = make_float2(v1.x, 0.f); d[5] = make_float2(v1.y, 0.f);
        d[6] = make_float2(v1.z, 0.f); d[7] = make_float2(v1.w, 0.f);
        apply_H(d, tw, lane);
        uint4* ur = (uint4*)(g_uh + grow * 256);
        ur[lane * 2] = make_uint4(pack_h2(d[0].x * sc, d[0].y * sc),
                                  pack_h2(d[1].x * sc, d[1].y * sc),
                                  pack_h2(d[2].x * sc, d[2].y * sc),
                                  pack_h2(d[3].x * sc, d[3].y * sc));
        ur[lane * 2 + 1] = make_uint4(pack_h2(d[4].x * sc, d[4].y * sc),
                                      pack_h2(d[5].x * sc, d[5].y * sc),
                                      pack_h2(d[6].x * sc, d[6].y * sc),
                                      pack_h2(d[7].x * sc, d[7].y * sc));
    }
}

// ---------------------------------------------------------------------------
// Column pass + magnitude + combine. Packed half2 tile (32.9KB).
// ---------------------------------------------------------------------------
#define COL_SMEM (32 * 257 * 4)

__global__ void __launch_bounds__(256, 5) col_kernel(const float* __restrict__ beta,
                                                     float* __restrict__ out) {
    extern __shared__ uint32_t tileu[];   // [32][257] packed half2 / f32 mag
    int t = threadIdx.x;
    int img = blockIdx.x >> 3;
    int c0 = (blockIdx.x & 7) << 5;
    size_t ibase = (size_t)img * 65536;
    const uint32_t* ub = g_uh + ibase;

    int cL = t & 31;
    int rg = t >> 5;
#pragma unroll 4
    for (int k = 0; k < 32; k++) {
        int r = rg + k * 8;
        tileu[cL * 257 + ((r & 7) << 5) + (r >> 3)] = ub[(size_t)r * 256 + c0 + cL];
    }
    __syncthreads();

    int lane = t & 31;
    int wp = t >> 5;
    FTw2 tw;
    make_tw2(lane, tw);
    const float sc = 1.0f / 256.0f;
#pragma unroll 1
    for (int cc = 0; cc < 4; cc++) {
        int cl = wp * 4 + cc;
        float2 d[8];
#pragma unroll
        for (int j = 0; j < 8; j++) d[j] = unpack_h2(tileu[cl * 257 + j * 32 + lane]);
        apply_H(d, tw, lane);
#pragma unroll
        for (int j = 0; j < 8; j++) {
            float vx = d[j].x * sc, vy = d[j].y * sc;
            tileu[cl * 257 + j * 32 + lane] = __float_as_uint(sqrtf(vx * vx + vy * vy));
        }
    }
    __syncthreads();

    float be = *beta;
    float a0 = be;
    float a1 = 1.0f - 2.0f * be;
    int c2 = (t & 15) * 2;
    int rg2 = t >> 4;
#pragma unroll 4
    for (int k = 0; k < 16; k++) {
        int r = rg2 + k * 16;
        size_t gg = ibase + (size_t)r * 256 + c0 + c2;
        float2 yf = unpack_h2(*(const uint32_t*)(g_yh + gg));
        int p = ((r & 7) << 5) + (r >> 3);
        float m0 = __uint_as_float(tileu[c2 * 257 + p]);
        float m1 = __uint_as_float(tileu[(c2 + 1) * 257 + p]);
        *(float2*)(out + gg) = make_float2(a0 * yf.x + a1 * m0, a0 * yf.y + a1 * m1);
    }
}

// ---------------------------------------------------------------------------
extern "C" void kernel_launch(void* const* d_in, const int* in_sizes, int n_in,
                              void* d_out, int out_size) {
    const float* x = (const float*)d_in[0];
    const float* w = (const float*)d_in[1];
    const float* beta = (const float*)d_in[2];
    float* out = (float*)d_out;

    cudaFuncSetAttribute(conv_mma_kernel, cudaFuncAttributeMaxDynamicSharedMemorySize, CONV_SMEM);
    cudaFuncSetAttribute(col_kernel, cudaFuncAttributeMaxDynamicSharedMemorySize, COL_SMEM);

    wprep_kernel<<<972, 256>>>(w);
    xprep_kernel<<<dim3(512, 3, 8), 256>>>(x);
    conv_mma_kernel<<<dim3(128, 8), 256, CONV_SMEM>>>();
    col_kernel<<<384 * 8, 256, COL_SMEM>>>(beta, out);
}

// round 10
// speedup vs baseline: 5.4142x; 1.3009x over previous
#include <cuda_runtime.h>
#include <cuda_fp16.h>
#include <math.h>
#include <stdint.h>

#define PI_F 3.14159265358979f

// ---------------------------------------------------------------------------
// Scratch (__device__ globals; no runtime alloc)
// ---------------------------------------------------------------------------
__device__ __half    g_yh[25165824];      // conv output fp16, pixel-shuffled (8,48,256,256)
__device__ __half    g_h[25165824];       // REAL part field h = H_s(rows) fp16
__device__ __half    g_xh[12582912];      // x transposed [b][hw][ic], fp16
__device__ __half    g_wimg[165888];      // weights fp16: 54 chunks x 3072 (LDS.128 frag layout)
__device__ float2    g_c[98304];          // per (image,row): c = Yhat(192)/256
__device__ float2    g_W[98304];          // per image: W = H(c) scaled

// ---------------------------------------------------------------------------
// mma.sync (fp16 in, f32 acc)
// ---------------------------------------------------------------------------
__device__ __forceinline__ void mma16816(float c[4],
                                         uint32_t a0, uint32_t a1, uint32_t a2, uint32_t a3,
                                         uint32_t b0, uint32_t b1) {
    asm volatile(
        "mma.sync.aligned.m16n8k16.row.col.f32.f16.f16.f32 "
        "{%0,%1,%2,%3}, {%4,%5,%6,%7}, {%8,%9}, {%0,%1,%2,%3};"
        : "+f"(c[0]), "+f"(c[1]), "+f"(c[2]), "+f"(c[3])
        : "r"(a0), "r"(a1), "r"(a2), "r"(a3), "r"(b0), "r"(b1));
}

__device__ __forceinline__ uint32_t smem_u32(const void* p) {
    uint32_t a;
    asm("{ .reg .u64 t; cvta.to.shared.u64 t, %1; cvt.u32.u64 %0, t; }" : "=r"(a) : "l"(p));
    return a;
}
__device__ __forceinline__ void cp_async16(uint32_t dst, const void* src) {
    asm volatile("cp.async.cg.shared.global [%0], [%1], 16;" :: "r"(dst), "l"(src));
}
__device__ __forceinline__ void cp_async16z(uint32_t dst, const void* src, bool inb) {
    int sz = inb ? 16 : 0;
    asm volatile("cp.async.cg.shared.global [%0], [%1], 16, %2;" :: "r"(dst), "l"(src), "r"(sz));
}
__device__ __forceinline__ void cp_commit() { asm volatile("cp.async.commit_group;"); }
__device__ __forceinline__ void cp_wait0()  { asm volatile("cp.async.wait_group 0;"); }

__device__ __forceinline__ uint32_t pack_h2(float a, float b) {
    uint32_t r;
    asm("cvt.rn.f16x2.f32 %0, %1, %2;" : "=r"(r) : "f"(b), "f"(a));
    return r;
}
__device__ __forceinline__ float2 unpack_h2(uint32_t v) {
    __half2 h = *reinterpret_cast<const __half2*>(&v);
    return __half22float2(h);
}
__device__ __forceinline__ float fsqrt_ap(float x) {
    float r;
    asm("sqrt.approx.f32 %0, %1;" : "=f"(r) : "f"(x));
    return r;
}

// ---------------------------------------------------------------------------
// Warp-FFT machinery
// ---------------------------------------------------------------------------
__device__ __forceinline__ float2 cadd(float2 a, float2 b) { return make_float2(a.x + b.x, a.y + b.y); }
__device__ __forceinline__ float2 csub(float2 a, float2 b) { return make_float2(a.x - b.x, a.y - b.y); }
__device__ __forceinline__ float2 cmul(float2 a, float2 b) {
    return make_float2(a.x * b.x - a.y * b.y, a.x * b.y + a.y * b.x);
}
__device__ __forceinline__ float2 cconj(float2 a) { return make_float2(a.x, -a.y); }
__device__ __forceinline__ float2 expi(float a) {
    float s, c;
    __sincosf(a, &s, &c);
    return make_float2(c, s);
}
__device__ __forceinline__ float2 shflxc(float2 v, int m) {
    v.x = __shfl_xor_sync(0xffffffffu, v.x, m);
    v.y = __shfl_xor_sync(0xffffffffu, v.y, m);
    return v;
}
// multiply by (-i)^s
__device__ __forceinline__ float2 rotmi(float2 v, int s) {
    s &= 3;
    if (s == 0) return v;
    if (s == 1) return make_float2(v.y, -v.x);
    if (s == 2) return make_float2(-v.x, -v.y);
    return make_float2(-v.y, v.x);
}

struct FTw2 { float2 ws0, ws1, ws2, ws3, mb; };

__device__ __forceinline__ void make_tw2(int lane, FTw2& t) {
    int brl = __brev((unsigned)lane) >> 27;
    t.ws0 = expi(-PI_F * (float)(lane & 15) / 16.0f);
    t.ws1 = expi(-PI_F * (float)(lane & 7) / 8.0f);
    const float R = 0.70710678118654752f;
    int a2 = lane & 3;
    t.ws2 = (a2 == 0) ? make_float2(1.f, 0.f)
          : (a2 == 1) ? make_float2(R, -R)
          : (a2 == 2) ? make_float2(0.f, -1.f)
                      : make_float2(-R, -R);
    t.ws3 = (lane & 1) ? make_float2(0.f, -1.f) : make_float2(1.f, 0.f);
    t.mb  = expi(-2.0f * PI_F * (float)brl / 256.0f);
}

__device__ __forceinline__ void xstage_fwd(float2 d[8], int S, float2 w, int lane) {
    bool hi = (lane & S) != 0;
#pragma unroll
    for (int j = 0; j < 8; j++) {
        float2 o = shflxc(d[j], S);
        d[j] = hi ? cmul(csub(o, d[j]), w) : cadd(d[j], o);
    }
}
__device__ __forceinline__ void xstage_unity(float2 d[8], int lane) {
    bool hi = (lane & 1) != 0;
#pragma unroll
    for (int j = 0; j < 8; j++) {
        float2 o = shflxc(d[j], 1);
        d[j] = hi ? csub(o, d[j]) : cadd(d[j], o);
    }
}
__device__ __forceinline__ void xstage_inv(float2 d[8], int S, float2 wc, int lane) {
    bool hi = (lane & S) != 0;
#pragma unroll
    for (int j = 0; j < 8; j++) {
        float2 pre = hi ? cmul(d[j], wc) : d[j];
        float2 o = shflxc(pre, S);
        d[j] = hi ? csub(o, pre) : cadd(pre, o);
    }
}

// Shared fwd prologue + mid (through S2 of in-register radix-8)
__device__ __forceinline__ void fftH_front(float2 d[8], const FTw2& t, int lane) {
    xstage_fwd(d, 16, t.ws0, lane);
    xstage_fwd(d, 8,  t.ws1, lane);
    xstage_fwd(d, 4,  t.ws2, lane);
    xstage_fwd(d, 2,  t.ws3, lane);
    xstage_unity(d, lane);
    {
        float2 m = t.mb;
        d[1] = cmul(d[1], m);
#pragma unroll
        for (int j = 2; j < 8; j++) { m = cmul(m, t.mb); d[j] = cmul(d[j], m); }
    }
    const float R = 0.70710678118654752f;
    const float2 W81 = make_float2(R, -R);
    const float2 W83 = make_float2(-R, -R);
    {
        float2 u, v, tt;
        u = d[0]; v = d[4]; d[0] = cadd(u, v); d[4] = csub(u, v);
        u = d[1]; v = d[5]; d[1] = cadd(u, v); d[5] = cmul(csub(u, v), W81);
        u = d[2]; v = d[6]; d[2] = cadd(u, v); tt = csub(u, v); d[6] = make_float2(tt.y, -tt.x);
        u = d[3]; v = d[7]; d[3] = cadd(u, v); d[7] = cmul(csub(u, v), W83);
    }
#pragma unroll
    for (int gg = 0; gg < 8; gg += 4) {
        float2 u, v, tt;
        u = d[gg];     v = d[gg + 2]; d[gg] = cadd(u, v);     d[gg + 2] = csub(u, v);
        u = d[gg + 1]; v = d[gg + 3]; tt = csub(u, v);
        d[gg + 1] = cadd(u, v); d[gg + 3] = make_float2(tt.y, -tt.x);
    }
}

// fold (mask) + inverse back half. zero192: zero bin 192 (H_s); ext: extract X192/X64.
__device__ __forceinline__ void fftH_back(float2 d[8], const FTw2& t, int lane,
                                          bool zero192, float2* X192, float2* X64) {
    {
        float2 p = cadd(d[0], d[1]);
        float2 q = csub(d[2], d[3]);
        float2 s64 = cadd(d[2], d[3]);
        float2 r = cadd(d[4], d[5]);
        float2 s = csub(d[6], d[7]);
        if (X192 && lane == 0) { *X192 = q; *X64 = s64; }
        if (zero192 && lane == 0) q = make_float2(0.f, 0.f);
        d[0] = cadd(p, q);
        d[2] = csub(p, q);
        d[1] = make_float2(p.x + q.y, p.y - q.x);
        d[3] = make_float2(p.x - q.y, p.y + q.x);
        d[4] = cadd(r, s);
        d[6] = csub(r, s);
        d[5] = make_float2(r.x + s.y, r.y - s.x);
        d[7] = make_float2(r.x - s.y, r.y + s.x);
    }
    const float R = 0.70710678118654752f;
    const float2 W81c = make_float2(R, R);
    const float2 W83c = make_float2(-R, R);
    {
        float2 a, v;
        a = d[0]; v = d[4];                d[0] = cadd(a, v); d[4] = csub(a, v);
        a = d[1]; v = cmul(d[5], W81c);    d[1] = cadd(a, v); d[5] = csub(a, v);
        a = d[2]; { float2 bq = d[6]; v = make_float2(-bq.y, bq.x); } d[2] = cadd(a, v); d[6] = csub(a, v);
        a = d[3]; v = cmul(d[7], W83c);    d[3] = cadd(a, v); d[7] = csub(a, v);
    }
    {
        float2 mc = cconj(t.mb);
        float2 m = mc;
        d[1] = cmul(d[1], m);
#pragma unroll
        for (int j = 2; j < 8; j++) { m = cmul(m, mc); d[j] = cmul(d[j], m); }
    }
    xstage_unity(d, lane);
    xstage_inv(d, 2,  cconj(t.ws3), lane);
    xstage_inv(d, 4,  cconj(t.ws2), lane);
    xstage_inv(d, 8,  cconj(t.ws1), lane);
    xstage_inv(d, 16, cconj(t.ws0), lane);
}

// Full H (asymmetric mask, complex input)
__device__ __forceinline__ void apply_H(float2 d[8], const FTw2& t, int lane) {
    fftH_front(d, t, lane);
    fftH_back(d, t, lane, false, nullptr, nullptr);
}
// H_s (symmetric mask, bin192 zeroed) + extraction of X192/X64 at lane 0
__device__ __forceinline__ void apply_Hs_ext(float2 d[8], const FTw2& t, int lane,
                                             float2& X192, float2& X64) {
    fftH_front(d, t, lane);
    fftH_back(d, t, lane, true, &X192, &X64);
}

// ---------------------------------------------------------------------------
// Prep 1: weights -> LDS.128-friendly fragment layout.
// Per chunk c (3072 halfs): b16 = (mglob*8 + g)*4 + tig, 8 halfs:
//   (rowg,k2t),(rowg,k2t+1),(rowg+8,k2t),(rowg+8,k2t+1),
//   (rowg,k8+2t),(rowg,k8+2t+1),(rowg+8,k8+2t),(rowg+8,k8+2t+1)
// ---------------------------------------------------------------------------
__global__ void wprep_kernel(const float* __restrict__ wgt) {
    int i = blockIdx.x * 256 + threadIdx.x;
    if (i >= 165888) return;
    int e = i % 3072;
    int c = i / 3072;
    int b16 = e >> 3, h8 = e & 7;
    int tig = b16 & 3, g = (b16 >> 2) & 7, mglob = b16 >> 5;
    int ah = h8 >> 1, par = h8 & 1;
    int oc = mglob * 16 + g + 8 * (ah & 1);
    int k = ((ah >> 1) ? 8 : 0) + 2 * tig + par;
    int tap = c / 6, icg = c % 6;
    int kh = tap / 3, kw = tap % 3;
    int ic = icg * 16 + k;
    float w = wgt[((size_t)oc * 96 + ic) * 9 + kh * 3 + kw];
    g_wimg[c * 3072 + e] = __float2half(w);
}

// ---------------------------------------------------------------------------
// Prep 2: transpose x (b,ic,h,w) f32 -> (b, hw, ic) fp16
// ---------------------------------------------------------------------------
__global__ void __launch_bounds__(256) xprep_kernel(const float* __restrict__ x) {
    __shared__ float tile[32][33];
    int t = threadIdx.x;
    int j = t & 31, i4 = t >> 5;
    int hw0 = blockIdx.x * 32;
    int ic0 = blockIdx.y * 32;
    int b = blockIdx.z;
#pragma unroll
    for (int r = 0; r < 4; r++) {
        int ic = ic0 + i4 * 4 + r;
        tile[i4 * 4 + r][j] = x[((size_t)b * 96 + ic) * 16384 + hw0 + j];
    }
    __syncthreads();
#pragma unroll
    for (int r = 0; r < 4; r++) {
        int hwl = i4 * 4 + r;
        float v = tile[j][hwl];
        size_t idx = ((size_t)b * 16384 + hw0 + hwl) * 96 + ic0 + j;
        g_xh[idx] = __float2half(v);
    }
}

// ---------------------------------------------------------------------------
// Conv implicit GEMM + fused packed row-H_s epilogue (2 real rows / FFT).
// ---------------------------------------------------------------------------
#define XS_ELEMS 40560
#define WOFF_B 81120
#define SLOT_B 6144
#define STG_STRIDE 264
#define CONV_SMEM (96 * STG_STRIDE * 4)   // 101376 >= WOFF_B + 2*SLOT_B = 93408

__global__ void __launch_bounds__(256, 2) conv_mma_kernel() {
    extern __shared__ char sd[];
    __half* xsH = (__half*)sd;
    __half* wring = (__half*)(sd + WOFF_B);

    int t = threadIdx.x;
    int h = blockIdx.x;
    int b = blockIdx.y;
    int wid = t >> 5, lane = t & 31;
    int g = lane >> 2, tig = lane & 3;
    int ocb16 = (wid >> 2) * 6;          // m16-block base (0 or 6)
    int pxbase = (wid & 3) * 32;

    uint32_t wring_s = smem_u32(wring);
    for (int i = t; i < 384; i += 256)
        cp_async16(wring_s + i * 16, (const char*)g_wimg + i * 16);
    cp_commit();

    {
        const __half* xb_h = g_xh + (size_t)b * 16384 * 96;
        uint32_t xs_s = smem_u32(xsH);
        for (int idx = t; idx < 4680; idx += 256) {
            int c16 = idx % 12;
            int ww = (idx / 12) % 130;
            int kh = idx / (12 * 130);
            int hp = h + kh - 1;
            int wp = ww - 1;
            bool inb = (hp >= 0 && hp < 128 && wp >= 0 && wp < 128);
            size_t src = inb ? (((size_t)hp * 128 + wp) * 96 + c16 * 8) : 0;
            int dst = kh * 13520 + ww * 104 + c16 * 8;
            cp_async16z(xs_s + dst * 2, xb_h + src, inb);
        }
    }
    cp_commit();
    cp_wait0();
    __syncthreads();

    float acc[6][4][4];
#pragma unroll
    for (int m = 0; m < 6; m++)
#pragma unroll
        for (int n = 0; n < 4; n++)
#pragma unroll
            for (int q = 0; q < 4; q++) acc[m][n][q] = 0.0f;

    for (int c = 0; c < 54; c++) {
        if (c < 53) {
            uint32_t dsts = wring_s + ((c + 1) & 1) * SLOT_B;
            const char* srcg = (const char*)g_wimg + (size_t)(c + 1) * SLOT_B;
            for (int i = t; i < 384; i += 256)
                cp_async16(dsts + i * 16, srcg + i * 16);
            cp_commit();
        }

        int tap = c / 6, icg = c % 6;
        int kh = tap / 3, kw = tap % 3;
        const uint4* wslot4 = (const uint4*)(wring + (c & 1) * 3072);

        uint32_t bh0[4], bh1[4];
        int rowb = kh * 130 + pxbase + kw + g;
        int icoff = icg * 16 + 2 * tig;
#pragma unroll
        for (int n = 0; n < 4; n++) {
            int off = (rowb + n * 8) * 104 + icoff;
            bh0[n] = *(const uint32_t*)(xsH + off);
            bh1[n] = *(const uint32_t*)(xsH + off + 8);
        }
#pragma unroll
        for (int m = 0; m < 6; m++) {
            uint4 av = wslot4[(ocb16 + m) * 32 + g * 4 + tig];
#pragma unroll
            for (int n = 0; n < 4; n++)
                mma16816(acc[m][n], av.x, av.y, av.z, av.w, bh0[n], bh1[n]);
        }
        if (c < 53) cp_wait0();
        __syncthreads();
    }

    // ---- Fused epilogue: stage pixel-shuffled D, packed row H_s ----
    float* stage = (float*)sd;
#pragma unroll
    for (int m = 0; m < 6; m++) {
#pragma unroll
        for (int n = 0; n < 4; n++) {
#pragma unroll
            for (int q = 0; q < 4; q++) {
                int oc = (ocb16 + m) * 16 + g + 8 * (q >> 1);
                int px = pxbase + n * 8 + 2 * tig + (q & 1);
                int r2 = oc >> 1;
                int col = 2 * px + (oc & 1);
                stage[r2 * STG_STRIDE + col] = acc[m][n][q];
            }
        }
    }
    __syncthreads();

    FTw2 tw;
    make_tw2(lane, tw);
    const float sc = 1.0f / 256.0f;
#pragma unroll 1
    for (int pr = 0; pr < 6; pr++) {
        int r2a = wid * 12 + 2 * pr;
        const float* rowA = stage + r2a * STG_STRIDE;
        const float* rowB = rowA + STG_STRIDE;
        float4 a0 = *(const float4*)(rowA + 8 * lane);
        float4 a1 = *(const float4*)(rowA + 8 * lane + 4);
        float4 b0 = *(const float4*)(rowB + 8 * lane);
        float4 b1 = *(const float4*)(rowB + 8 * lane + 4);
        int cch = wid * 6 + pr;                    // r2a >> 1
        size_t rowImgA = ((size_t)b * 48 + cch) * 256 + 2 * h;   // pbit 0
        // y stores (both rows)
        ((uint4*)(g_yh + rowImgA * 256))[lane] =
            make_uint4(pack_h2(a0.x, a0.y), pack_h2(a0.z, a0.w),
                       pack_h2(a1.x, a1.y), pack_h2(a1.z, a1.w));
        ((uint4*)(g_yh + (rowImgA + 1) * 256))[lane] =
            make_uint4(pack_h2(b0.x, b0.y), pack_h2(b0.z, b0.w),
                       pack_h2(b1.x, b1.y), pack_h2(b1.z, b1.w));
        // packed z = rowA + i*rowB
        float2 d[8];
        d[0] = make_float2(a0.x, b0.x); d[1] = make_float2(a0.y, b0.y);
        d[2] = make_float2(a0.z, b0.z); d[3] = make_float2(a0.w, b0.w);
        d[4] = make_float2(a1.x, b1.x); d[5] = make_float2(a1.y, b1.y);
        d[6] = make_float2(a1.z, b1.z); d[7] = make_float2(a1.w, b1.w);
        float2 X192 = make_float2(0.f, 0.f), X64 = make_float2(0.f, 0.f);
        apply_Hs_ext(d, tw, lane, X192, X64);
        // h stores (real parts -> row A, imag -> row B)
        ((uint4*)(g_h + rowImgA * 256))[lane] =
            make_uint4(pack_h2(d[0].x * sc, d[1].x * sc), pack_h2(d[2].x * sc, d[3].x * sc),
                       pack_h2(d[4].x * sc, d[5].x * sc), pack_h2(d[6].x * sc, d[7].x * sc));
        ((uint4*)(g_h + (rowImgA + 1) * 256))[lane] =
            make_uint4(pack_h2(d[0].y * sc, d[1].y * sc), pack_h2(d[2].y * sc, d[3].y * sc),
                       pack_h2(d[4].y * sc, d[5].y * sc), pack_h2(d[6].y * sc, d[7].y * sc));
        if (lane == 0) {
            float2 ca = make_float2((X192.x + X64.x) * 0.5f * sc,
                                    (X192.y - X64.y) * 0.5f * sc);
            float2 inner = make_float2((X192.x - X64.x) * 0.5f * sc,
                                       (X192.y + X64.y) * 0.5f * sc);
            float2 cb = make_float2(inner.y, -inner.x);     // -i * inner
            g_c[rowImgA] = ca;
            g_c[rowImgA + 1] = cb;
        }
    }
}

// ---------------------------------------------------------------------------
// W kernel: per image, W = H(c) (full complex H), scaled.
// ---------------------------------------------------------------------------
__global__ void wcol_kernel() {
    int lane = threadIdx.x;
    int img = blockIdx.x;
    FTw2 tw;
    make_tw2(lane, tw);
    float2 d[8];
#pragma unroll
    for (int j = 0; j < 8; j++) d[j] = g_c[img * 256 + 8 * lane + j];
    apply_H(d, tw, lane);
    const float sc = 1.0f / 256.0f;
#pragma unroll
    for (int j = 0; j < 8; j++)
        g_W[img * 256 + 8 * lane + j] = make_float2(d[j].x * sc, d[j].y * sc);
}

// ---------------------------------------------------------------------------
// Column pass: packed 2 real cols per H_s + corrections + magnitude + combine.
// ---------------------------------------------------------------------------
#define COL_SMEM (16 * 257 * 4 + 2 * 256 * 4)   // tileP + Wre + Wim = 18496

__global__ void __launch_bounds__(256, 5) col_kernel(const float* __restrict__ beta,
                                                     float* __restrict__ out) {
    extern __shared__ uint32_t sm[];
    uint32_t* tileP = sm;                   // [16][257] packed half2 (2 cols)
    float* Wre = (float*)(sm + 16 * 257);
    float* Wim = Wre + 256;

    int t = threadIdx.x;
    int img = blockIdx.x >> 3;
    int c0 = (blockIdx.x & 7) << 5;
    size_t ibase = (size_t)img * 65536;
    const uint32_t* hb = (const uint32_t*)g_h + ibase / 2;

    int p = t & 15, rg = t >> 4;
#pragma unroll 4
    for (int k = 0; k < 16; k++) {
        int r = rg + k * 16;
        tileP[p * 257 + ((r & 7) << 5) + (r >> 3)] = hb[r * 128 + (c0 >> 1) + p];
    }
    {
        float2 w = g_W[img * 256 + t];
        int pos = ((t & 7) << 5) | (t >> 3);
        Wre[pos] = w.x;
        Wim[pos] = w.y;
    }
    __syncthreads();

    int lane = t & 31, wp = t >> 5;
    FTw2 tw;
    make_tw2(lane, tw);
    const float sc = 1.0f / 256.0f;
#pragma unroll 1
    for (int cc = 0; cc < 2; cc++) {
        int pi = wp * 2 + cc;
        int n0 = c0 + 2 * pi;
        float2 d[8];
#pragma unroll
        for (int j = 0; j < 8; j++) d[j] = unpack_h2(tileP[pi * 257 + j * 32 + lane]);
        float2 X192 = make_float2(0.f, 0.f), X64 = make_float2(0.f, 0.f);
        apply_Hs_ext(d, tw, lane, X192, X64);
        // broadcast extraction from lane 0
        float x192x = __shfl_sync(0xffffffffu, X192.x, 0);
        float x192y = __shfl_sync(0xffffffffu, X192.y, 0);
        float x64x  = __shfl_sync(0xffffffffu, X64.x, 0);
        float x64y  = __shfl_sync(0xffffffffu, X64.y, 0);
        float2 d0 = make_float2((x192x + x64x) * 0.5f * sc, (x192y - x64y) * 0.5f * sc);
        float2 inner = make_float2((x192x - x64x) * 0.5f * sc, (x192y + x64y) * 0.5f * sc);
        float2 d1 = make_float2(inner.y, -inner.x);
        int rot0 = n0 & 3, rot1 = (n0 + 1) & 3;
#pragma unroll
        for (int j = 0; j < 8; j++) {
            int pos = j * 32 + lane;
            float2 Wm = make_float2(Wre[pos], Wim[pos]);
            float2 w0 = rotmi(Wm, rot0);
            float2 w1 = rotmi(Wm, rot1);
            float2 cj0 = rotmi(d0, j);
            float2 cj1 = rotmi(d1, j);
            float vr0 = d[j].x * sc + cj0.x + w0.x;
            float vi0 = cj0.y + w0.y;
            float vr1 = d[j].y * sc + cj1.x + w1.x;
            float vi1 = cj1.y + w1.y;
            float m0 = fsqrt_ap(vr0 * vr0 + vi0 * vi0);
            float m1 = fsqrt_ap(vr1 * vr1 + vi1 * vi1);
            tileP[pi * 257 + pos] = pack_h2(m0, m1);
        }
    }
    __syncthreads();

    float be = *beta;
    float a0c = be;
    float a1c = 1.0f - 2.0f * be;
    int cp = t & 15, rg2 = t >> 4;
#pragma unroll 4
    for (int k = 0; k < 16; k++) {
        int r = rg2 + k * 16;
        size_t gg = ibase + (size_t)r * 256 + c0 + 2 * cp;
        float2 yf = unpack_h2(*(const uint32_t*)(g_yh + gg));
        int pos = ((r & 7) << 5) + (r >> 3);
        float2 mg = unpack_h2(tileP[cp * 257 + pos]);
        *(float2*)(out + gg) = make_float2(a0c * yf.x + a1c * mg.x,
                                           a0c * yf.y + a1c * mg.y);
    }
}

// ---------------------------------------------------------------------------
extern "C" void kernel_launch(void* const* d_in, const int* in_sizes, int n_in,
                              void* d_out, int out_size) {
    const float* x = (const float*)d_in[0];
    const float* w = (const float*)d_in[1];
    const float* beta = (const float*)d_in[2];
    float* out = (float*)d_out;

    cudaFuncSetAttribute(conv_mma_kernel, cudaFuncAttributeMaxDynamicSharedMemorySize, CONV_SMEM);
    cudaFuncSetAttribute(col_kernel, cudaFuncAttributeMaxDynamicSharedMemorySize, COL_SMEM);

    wprep_kernel<<<648, 256>>>(w);
    xprep_kernel<<<dim3(512, 3, 8), 256>>>(x);
    conv_mma_kernel<<<dim3(128, 8), 256, CONV_SMEM>>>();
    wcol_kernel<<<384, 32>>>();
    col_kernel<<<384 * 8, 256, COL_SMEM>>>(beta, out);
}